// round 8
// baseline (speedup 1.0000x reference)
#include <cuda_runtime.h>
#include <cuda_fp16.h>

#define BB 64
#define SS 128
#define DD 64
#define BS (BB*SS)

// -------- scratch (no allocations allowed) --------
__device__ __align__(16) float g_q [BS*DD];
__device__ __align__(16) float g_k [BS*DD];
__device__ __align__(16) float g_v [BS*DD];
__device__ __align__(16) float g_h2[BS*DD];

__device__ __forceinline__ float fast_sigmoid(float z) {
    float t;
    asm("tanh.approx.f32 %0, %1;" : "=f"(t) : "f"(0.5f * z));
    return fmaf(0.5f, t, 0.5f);
}
__device__ __forceinline__ __half2 tanh2_fast(__half2 z) {
    unsigned zu = *reinterpret_cast<unsigned*>(&z), tu;
    asm("tanh.approx.f16x2 %0, %1;" : "=r"(tu) : "r"(zu));
    return *reinterpret_cast<__half2*>(&tu);
}
__device__ __forceinline__ float warp_max(float v) {
#pragma unroll
    for (int o = 16; o; o >>= 1) v = fmaxf(v, __shfl_xor_sync(0xffffffffu, v, o));
    return v;
}
__device__ __forceinline__ float warp_sum(float v) {
#pragma unroll
    for (int o = 16; o; o >>= 1) v += __shfl_xor_sync(0xffffffffu, v, o);
    return v;
}

// ===== kernel 1: EOPA (emb gather folded) + h = prelu(x@Ws+nm@Wn) + q/k/v ===
// grid (4, BB), 256 threads; block handles rows i = ih*32 .. +31
__global__ void __launch_bounds__(256) k_eopa(
        const int* __restrict__ items, const int* __restrict__ A,
        const int* __restrict__ eo, const float* __restrict__ emb,
        const float* __restrict__ Ws, const float* __restrict__ Wn,
        const float* __restrict__ p1,
        const float* __restrict__ Wq, const float* __restrict__ bq,
        const float* __restrict__ Wk, const float* __restrict__ Wv) {
    int b = blockIdx.y, ih = blockIdx.x, tid = threadIdx.x;
    __shared__ unsigned char Ab[SS*SS];      // 16KB: A[b] as 0/1 bytes
    __shared__ __half2 xs2[SS*32];           // 16KB: x[b] as half2
    __shared__ unsigned char cnd[SS*32];     // 4KB: cond[j][i_local]
    __shared__ float buf[32*DD];             // 8KB: nm, then h
    __shared__ int itm[SS];                  // item ids

    if (tid < SS) itm[tid] = items[b*SS + tid];
    __syncthreads();

    const int4* Ag = (const int4*)(A + b*SS*SS);
    for (int t = tid; t < SS*SS/4; t += 256) {
        int4 a = Ag[t];
        uchar4 c;
        c.x = (a.x == 1); c.y = (a.y == 1); c.z = (a.z == 1); c.w = (a.w == 1);
        *(uchar4*)&Ab[t*4] = c;
    }
    for (int t = tid; t < SS*32; t += 256) {
        int row = t >> 5, dp = t & 31;
        float2 xf = *(const float2*)&emb[itm[row]*DD + dp*2];
        xs2[t] = __floats2half2_rn(xf.x, xf.y);
    }
    __syncthreads();

    // cond[j][il] = (A[b, j, eo[b,j, ih*32+il]] == 1)
    const int* eob = eo + b*SS*SS + ih*32;
    for (int t = tid; t < SS*32; t += 256) {
        int j = t >> 5, il = t & 31;
        int e = eob[j*SS + il];
        cnd[t] = Ab[j*SS + e];
    }
    __syncthreads();

    // neighbor max-pool in half2: thread = (dpair, grp); 4 rows per grp
    {
        int dp = tid & 31, grp = tid >> 5;
        __half2 z = __float2half2_rn(0.f);
        __half2 m[4] = {z, z, z, z};
        for (int j = 0; j < SS; j++) {
            __half2 xv = xs2[j*32 + dp];
#pragma unroll
            for (int t = 0; t < 4; t++) {
                bool c = cnd[j*32 + grp*4 + t] != 0;
                m[t] = __hmax2(m[t], c ? xv : z);
            }
        }
#pragma unroll
        for (int t = 0; t < 4; t++) {
            float2 f = __half22float2(m[t]);
            int r = grp*4 + t;
            buf[r*DD + dp*2]     = f.x;
            buf[r*DD + dp*2 + 1] = f.y;
        }
    }
    __syncthreads();

    // h = prelu(x@Ws + nm@Wn); x read from emb (L1 broadcast)
    int d = tid & 63, g4 = tid >> 6;         // 8 rows per g4
    int it8[8];
#pragma unroll
    for (int t = 0; t < 8; t++) it8[t] = itm[ih*32 + g4*8 + t];
    float acc[8];
#pragma unroll
    for (int t = 0; t < 8; t++) acc[t] = 0.f;
    for (int c = 0; c < DD; c++) {
        float ws = Ws[c*DD + d], wn = Wn[c*DD + d];
#pragma unroll
        for (int t = 0; t < 8; t++) {
            acc[t] = fmaf(emb[it8[t]*DD + c], ws, acc[t]);
            acc[t] = fmaf(buf[(g4*8 + t)*DD + c], wn, acc[t]);
        }
    }
    float a1 = p1[d];
#pragma unroll
    for (int t = 0; t < 8; t++) { float v = acc[t]; acc[t] = v >= 0.f ? v : a1*v; }
    __syncthreads();
#pragma unroll
    for (int t = 0; t < 8; t++) buf[(g4*8 + t)*DD + d] = acc[t];   // h
    __syncthreads();

    // fused q/k/v projection
    float aq[8], ak[8], av[8];
    float bqd = bq[d];
#pragma unroll
    for (int t = 0; t < 8; t++) { aq[t] = bqd; ak[t] = 0.f; av[t] = 0.f; }
    for (int c = 0; c < DD; c++) {
        float wq = Wq[c*DD + d], wk = Wk[c*DD + d], wv = Wv[c*DD + d];
#pragma unroll
        for (int t = 0; t < 8; t++) {
            float hv = buf[(g4*8 + t)*DD + c];
            aq[t] = fmaf(hv, wq, aq[t]);
            ak[t] = fmaf(hv, wk, ak[t]);
            av[t] = fmaf(hv, wv, av[t]);
        }
    }
#pragma unroll
    for (int t = 0; t < 8; t++) {
        int gi = (b*SS + ih*32 + g4*8 + t)*DD + d;
        g_q[gi] = aq[t];
        g_k[gi] = ak[t];
        g_v[gi] = av[t];
    }
}

// ===== kernel 2: fused attention (logits + softmax + a@v), no g_aw =========
// grid (2, BB), 512 threads (16 warps); warp w handles j_local = w*4 .. +3
__global__ void __launch_bounds__(512) k_attn(const int* __restrict__ A,
                                              const float* __restrict__ we,
                                              const float* __restrict__ prelu2) {
    int b = blockIdx.y, jh = blockIdx.x;
    int tid = threadIdx.x, w = tid >> 5, lane = tid & 31;
    __shared__ __half2 ks2[SS*33];           // 16.9KB: 0.5*k[b], pad 33
    __shared__ __half2 vs2[SS*32];           // 16KB:  v[b]
    __shared__ unsigned int msk[64][4];      // 1KB:   activity bitmasks per j
    __shared__ __half2 qw2[16][32];          // 2KB:   0.5*q per warp
    __shared__ unsigned char slist[16][SS];  // 2KB
    __shared__ __half awb[16][2*SS];         // 8KB:   aw interleaved (j0,j1)
    __shared__ __half2 wes2[32];             // we half2
    __shared__ float wesf[DD];               // we f32

    const float2* kb = (const float2*)(g_k + b*SS*DD);
    const float2* vb = (const float2*)(g_v + b*SS*DD);
    for (int t = tid; t < SS*32; t += 512) {
        int row = t >> 5, dp = t & 31;
        float2 kf = kb[t];
        ks2[row*33 + dp] = __floats2half2_rn(0.5f*kf.x, 0.5f*kf.y);
        float2 vf = vb[t];
        vs2[t] = __floats2half2_rn(vf.x, vf.y);
    }
    if (tid < 32) {
        float2 wf = *(const float2*)&we[tid*2];
        wes2[tid] = __floats2half2_rn(wf.x, wf.y);
    }
    if (tid >= 64 && tid < 128) wesf[tid - 64] = we[tid - 64];
    if (tid >= 128 && tid < 384) {
        int t = tid - 128;
        int jl = t >> 2, ii = t & 3;
        const int* Ac = A + (b*SS + ii*32)*SS + jh*64 + jl;
        unsigned m = 0;
#pragma unroll
        for (int l = 0; l < 32; l++) m |= (unsigned)(Ac[l*SS] == 1) << l;
        msk[jl][ii] = m;
    }
    __syncthreads();

    float e0;
    {
        float s = 0.f;
#pragma unroll
        for (int c = 0; c < DD; c++) s += wesf[c];
        e0 = 0.5f * s;                       // logit of an inactive edge
    }
    float2 pr = *(const float2*)&prelu2[lane*2];

    for (int pair = 0; pair < 2; pair++) {
        // ---- phase A: logits + softmax for j(par=0) and j(par=1) ----
        for (int par = 0; par < 2; par++) {
            int jl = (w << 2) + (pair << 1) + par;
            int j  = (jh << 6) + jl;
            {
                float2 qf = *(const float2*)&g_q[(b*SS + j)*DD + lane*2];
                qw2[w][lane] = __floats2half2_rn(0.5f*qf.x, 0.5f*qf.y);
            }
            __syncwarp();

            // compaction from bitmask
            int n = 0;
#pragma unroll
            for (int ii = 0; ii < 4; ii++) {
                unsigned m = msk[jl][ii];
                if ((m >> lane) & 1u)
                    slist[w][n + __popc(m & ((1u << lane) - 1u))] =
                        (unsigned char)(ii*32 + lane);
                n += __popc(m);
            }
            __syncwarp();
            int nIter = (n + 31) >> 5;

            float sreg[4];
#pragma unroll
            for (int it = 0; it < 4; it++) {
                sreg[it] = -1e30f;
                if (it < nIter) {
                    int idx = (it << 5) + lane;
                    bool val = idx < n;
                    int i = val ? (int)slist[w][idx] : lane;
                    const __half2* kr = &ks2[i*33];
                    float s0 = 0.f, s1 = 0.f;
#pragma unroll
                    for (int c8 = 0; c8 < 4; c8++) {
                        __half2 sacc = __float2half2_rn(0.f);
#pragma unroll
                        for (int dd = c8*8; dd < c8*8 + 8; dd++) {
                            __half2 z = __hadd2(kr[dd], qw2[w][dd]);
                            sacc = __hfma2(wes2[dd], tanh2_fast(z), sacc);
                        }
                        float2 f = __half22float2(sacc);
                        s0 += f.x; s1 += f.y;
                    }
                    if (val) sreg[it] = fmaf(0.5f, s0 + s1, e0);
                }
            }

            float mx = e0;
#pragma unroll
            for (int it = 0; it < 4; it++)
                if (it < nIter) mx = fmaxf(mx, warp_max(sreg[it]));
            float sum = (float)(SS - n) * __expf(e0 - mx);
            float preg[4];
#pragma unroll
            for (int it = 0; it < 4; it++)
                if (it < nIter) { preg[it] = __expf(sreg[it] - mx); sum += warp_sum(preg[it]); }
            float inv = __fdividef(1.f, sum);
            float a0 = __expf(e0 - mx) * inv;

            // dense fill with a0, then scatter active weights
            __half ha0 = __float2half(a0);
#pragma unroll
            for (int k2 = 0; k2 < 4; k2++)
                awb[w][2*(lane + 32*k2) + par] = ha0;
            __syncwarp();
#pragma unroll
            for (int it = 0; it < 4; it++)
                if (it < nIter) {
                    int idx = (it << 5) + lane;
                    if (idx < n)
                        awb[w][2*(int)slist[w][idx] + par] = __float2half(preg[it]*inv);
                }
            __syncwarp();
        }

        // ---- phase B: h2 for the two j's, v shared across both ----
        int j0 = (jh << 6) + (w << 2) + (pair << 1), j1 = j0 + 1;
        float x0 = 0.f, y0 = 0.f, x1 = 0.f, y1 = 0.f;
#pragma unroll 8
        for (int i = 0; i < SS; i++) {
            float2 vf = __half22float2(vs2[i*32 + lane]);
            __half2 aw2 = *(__half2*)&awb[w][2*i];
            float2 af = __half22float2(aw2);
            x0 = fmaf(af.x, vf.x, x0); y0 = fmaf(af.x, vf.y, y0);
            x1 = fmaf(af.y, vf.x, x1); y1 = fmaf(af.y, vf.y, y1);
        }
        float2 o0, o1;
        o0.x = x0 >= 0.f ? x0 : pr.x*x0;  o0.y = y0 >= 0.f ? y0 : pr.y*y0;
        o1.x = x1 >= 0.f ? x1 : pr.x*x1;  o1.y = y1 >= 0.f ? y1 : pr.y*y1;
        *(float2*)&g_h2[(b*SS + j0)*DD + lane*2] = o0;
        *(float2*)&g_h2[(b*SS + j1)*DD + lane*2] = o1;
        __syncwarp();
    }
}

// ===== kernel 3: readout + session representation ==========================
// grid BB, 512 threads
__global__ void __launch_bounds__(512) k_readout(
        const int* __restrict__ last_nodes,
        const float* __restrict__ Wu,  const float* __restrict__ bu,
        const float* __restrict__ Wvr, const float* __restrict__ wer,
        const float* __restrict__ prelu3, const float* __restrict__ W_sr,
        float* __restrict__ out) {
    int b = blockIdx.x, tid = threadIdx.x, lane = tid & 31;
    __shared__ float h2s[SS*DD];             // 32KB
    __shared__ float xlast[DD], xv[DD], eatt[SS], outv[DD];
    __shared__ float red[4];
    __shared__ float epart[SS][2];
    __shared__ float psum2[8][DD];

    const float4* hb4 = (const float4*)(g_h2 + b*SS*DD);
    float4* h4 = (float4*)h2s;
    for (int t = tid; t < SS*DD/4; t += 512) h4[t] = hb4[t];
    __syncthreads();

    int ln = last_nodes[b];
    if (tid < DD) xlast[tid] = h2s[ln*DD + tid];
    __syncthreads();
    if (tid < DD) {
        float a = 0.f;
#pragma unroll
        for (int c = 0; c < DD; c++) a = fmaf(xlast[c], Wvr[c*DD + tid], a);
        xv[tid] = a;
    }
    __syncthreads();

    // eatt[s] = sum_d wer[d]*sigmoid(h2[s]@Wu[:,d] + bu[d] + xv[d])
    int d = tid & 63, grp = tid >> 6;        // grp 0..7, items s = grp*16 .. +15
    {
        float acc[16];
        float bx = bu[d] + xv[d];
#pragma unroll
        for (int t = 0; t < 16; t++) acc[t] = bx;
        for (int c = 0; c < DD; c++) {
            float wu = Wu[c*DD + d];
#pragma unroll
            for (int t = 0; t < 16; t++)
                acc[t] = fmaf(h2s[(grp*16 + t)*DD + c], wu, acc[t]);
        }
        float wr = wer[d];
        int halfd = (tid >> 5) & 1;
#pragma unroll
        for (int t = 0; t < 16; t++) {
            float val = wr * fast_sigmoid(acc[t]);
            val = warp_sum(val);
            if (lane == 0) epart[grp*16 + t][halfd] = val;
        }
    }
    __syncthreads();
    if (tid < SS) eatt[tid] = epart[tid][0] + epart[tid][1];
    __syncthreads();

    // softmax over s
    float alpha;
    {
        float v = (tid < SS) ? eatt[tid] : -1e30f;
        v = warp_max(v);
        if ((tid & 31) == 0 && tid < SS) red[tid >> 5] = v;
        __syncthreads();
        float mx = fmaxf(fmaxf(red[0], red[1]), fmaxf(red[2], red[3]));
        float ex = (tid < SS) ? __expf(eatt[tid] - mx) : 0.f;
        __syncthreads();
        float sv = warp_sum(ex);
        if ((tid & 31) == 0 && tid < SS) red[tid >> 5] = sv;
        __syncthreads();
        float tot = red[0] + red[1] + red[2] + red[3];
        alpha = ex * __fdividef(1.f, tot);
    }
    __syncthreads();
    if (tid < SS) eatt[tid] = alpha;
    __syncthreads();

    // out[d] = prelu3( sum_s alpha[s]*h2[s][d] )
    {
        float acc = 0.f;
#pragma unroll
        for (int t = 0; t < 16; t++) {
            int s = grp*16 + t;
            acc = fmaf(eatt[s], h2s[s*DD + d], acc);
        }
        psum2[grp][d] = acc;
    }
    __syncthreads();
    if (tid < DD) {
        float sm = 0.f;
#pragma unroll
        for (int g = 0; g < 8; g++) sm += psum2[g][tid];
        float a = prelu3[tid];
        outv[tid] = sm >= 0.f ? sm : a * sm;
    }
    __syncthreads();
    if (tid < DD) {
        float a = 0.f;
#pragma unroll
        for (int c = 0; c < DD; c++) {
            a = fmaf(outv[c],  W_sr[c*DD + tid], a);
            a = fmaf(xlast[c], W_sr[(DD + c)*DD + tid], a);
        }
        out[b*DD + tid] = a;
    }
}

extern "C" void kernel_launch(void* const* d_in, const int* in_sizes, int n_in,
                              void* d_out, int out_size) {
    const int*   items      = (const int*)  d_in[0];
    const int*   A          = (const int*)  d_in[1];
    const int*   eo         = (const int*)  d_in[2];
    const int*   last_nodes = (const int*)  d_in[3];
    // d_in[4] = mask (all true)
    const float* emb        = (const float*)d_in[5];
    const float* W_self     = (const float*)d_in[6];
    const float* W_neigh    = (const float*)d_in[7];
    const float* prelu1     = (const float*)d_in[8];
    const float* Wq         = (const float*)d_in[9];
    const float* bq         = (const float*)d_in[10];
    const float* Wk         = (const float*)d_in[11];
    const float* Wv         = (const float*)d_in[12];
    const float* we         = (const float*)d_in[13];
    const float* prelu2     = (const float*)d_in[14];
    const float* Wu         = (const float*)d_in[15];
    const float* bu         = (const float*)d_in[16];
    const float* Wvr        = (const float*)d_in[17];
    const float* wer        = (const float*)d_in[18];
    const float* prelu3     = (const float*)d_in[19];
    const float* W_sr       = (const float*)d_in[20];
    float* out = (float*)d_out;

    k_eopa<<<dim3(4, BB), 256>>>(items, A, eo, emb, W_self, W_neigh, prelu1,
                                 Wq, bq, Wk, Wv);
    k_attn<<<dim3(2, BB), 512>>>(A, we, prelu2);
    k_readout<<<BB, 512>>>(last_nodes, Wu, bu, Wvr, wer, prelu3, W_sr, out);
}

// round 10
// speedup vs baseline: 1.3156x; 1.3156x over previous
#include <cuda_runtime.h>
#include <cuda_fp16.h>

#define BB 64
#define SS 128
#define DD 64
#define BS (BB*SS)

// -------- scratch (no allocations allowed) --------
__device__ __align__(16) float g_x [BS*DD];
__device__ __align__(16) float g_q [BS*DD];
__device__ __align__(16) float g_k [BS*DD];
__device__ __align__(16) float g_v [BS*DD];
__device__ __align__(16) float g_h2[BS*DD];

__device__ __forceinline__ float fast_sigmoid(float z) {
    float t;
    asm("tanh.approx.f32 %0, %1;" : "=f"(t) : "f"(0.5f * z));
    return fmaf(0.5f, t, 0.5f);
}
__device__ __forceinline__ __half2 tanh2_fast(__half2 z) {
    unsigned zu = *reinterpret_cast<unsigned*>(&z), tu;
    asm("tanh.approx.f16x2 %0, %1;" : "=r"(tu) : "r"(zu));
    return *reinterpret_cast<__half2*>(&tu);
}
__device__ __forceinline__ float warp_max(float v) {
#pragma unroll
    for (int o = 16; o; o >>= 1) v = fmaxf(v, __shfl_xor_sync(0xffffffffu, v, o));
    return v;
}
__device__ __forceinline__ float warp_sum(float v) {
#pragma unroll
    for (int o = 16; o; o >>= 1) v += __shfl_xor_sync(0xffffffffu, v, o);
    return v;
}

// -------- kernel 1: x = emb[items] --------
__global__ void k_gather(const int* __restrict__ items, const float* __restrict__ emb) {
    int idx = blockIdx.x * blockDim.x + threadIdx.x;
    int bs = idx >> 6, d = idx & 63;
    g_x[idx] = emb[items[bs] * DD + d];
}

// -------- kernel 2: EOPA max + h = prelu(x@Ws + nm@Wn)  +  fused q/k/v --------
// grid (4, BB), 256 threads; block handles 32 rows i = ih*32 .. +31
__global__ void __launch_bounds__(256) k_eopa(
        const int* __restrict__ A, const int* __restrict__ eo,
        const float* __restrict__ Ws, const float* __restrict__ Wn,
        const float* __restrict__ p1,
        const float* __restrict__ Wq, const float* __restrict__ bq,
        const float* __restrict__ Wk, const float* __restrict__ Wv) {
    int b = blockIdx.y, ih = blockIdx.x;
    int tid = threadIdx.x;
    __shared__ float xs[SS*DD];              // 32KB: x[b]
    __shared__ unsigned char cnd[SS*32];     // 4KB: cond[j][i_local]
    __shared__ float buf[32*DD];             // 8KB: nms, then hs

    const float4* xb4 = (const float4*)(g_x + b*SS*DD);
    float4* xs4 = (float4*)xs;
    for (int t = tid; t < SS*DD/4; t += 256) xs4[t] = xb4[t];

    const int* eob = eo + b*SS*SS;
    const int* Ab  = A  + b*SS*SS;
    for (int t = tid; t < SS*32; t += 256) {
        int j = t >> 5, il = t & 31;
        int e = eob[j*SS + ih*32 + il];
        cnd[t] = (Ab[j*SS + e] == 1);
    }
    __syncthreads();

    int d = tid & 63, grp = tid >> 6;        // grp 0..3, items i_local = grp*8 + t
    float m[8];
#pragma unroll
    for (int t = 0; t < 8; t++) m[t] = -1e30f;
    for (int j = 0; j < SS; j++) {
        float xv = xs[j*DD + d];
#pragma unroll
        for (int t = 0; t < 8; t++) {
            bool c = cnd[j*32 + grp*8 + t] != 0;
            m[t] = fmaxf(m[t], c ? xv : 0.f);
        }
    }
#pragma unroll
    for (int t = 0; t < 8; t++) buf[(grp*8+t)*DD + d] = m[t];
    __syncthreads();

    float acc[8];
#pragma unroll
    for (int t = 0; t < 8; t++) acc[t] = 0.f;
    for (int c = 0; c < DD; c++) {
        float ws = Ws[c*DD + d], wn = Wn[c*DD + d];
#pragma unroll
        for (int t = 0; t < 8; t++) {
            int il = grp*8 + t;
            acc[t] = fmaf(xs[(ih*32+il)*DD + c], ws, acc[t]);
            acc[t] = fmaf(buf[il*DD + c], wn, acc[t]);
        }
    }
    float a1 = p1[d];
#pragma unroll
    for (int t = 0; t < 8; t++) { float v = acc[t]; acc[t] = v >= 0.f ? v : a1*v; }
    __syncthreads();                          // all nms reads done
#pragma unroll
    for (int t = 0; t < 8; t++) buf[(grp*8+t)*DD + d] = acc[t];   // hs
    __syncthreads();

    // fused q/k/v projection on the 32 rows
    float aq[8], ak[8], av[8];
    float bqd = bq[d];
#pragma unroll
    for (int t = 0; t < 8; t++) { aq[t] = bqd; ak[t] = 0.f; av[t] = 0.f; }
    for (int c = 0; c < DD; c++) {
        float wq = Wq[c*DD + d], wk = Wk[c*DD + d], wv = Wv[c*DD + d];
#pragma unroll
        for (int t = 0; t < 8; t++) {
            float hv = buf[(grp*8+t)*DD + c];
            aq[t] = fmaf(hv, wq, aq[t]);
            ak[t] = fmaf(hv, wk, ak[t]);
            av[t] = fmaf(hv, wv, av[t]);
        }
    }
#pragma unroll
    for (int t = 0; t < 8; t++) {
        int gi = (b*SS + ih*32 + grp*8 + t)*DD + d;
        g_q[gi] = aq[t];
        g_k[gi] = ak[t];
        g_v[gi] = av[t];
    }
}

// ===== kernel 3: fused attention (logits + softmax + a@v), no g_aw =========
// grid (2, BB), 512 threads (16 warps); warp w handles j_local = w*4 .. +3
__global__ void __launch_bounds__(512) k_attn(const int* __restrict__ A,
                                              const float* __restrict__ we,
                                              const float* __restrict__ prelu2) {
    int b = blockIdx.y, jh = blockIdx.x;
    int tid = threadIdx.x, w = tid >> 5, lane = tid & 31;
    __shared__ __half2 ks2[SS*33];           // 16.9KB: 0.5*k[b], pad 33
    __shared__ __half2 vs2[SS*32];           // 16KB:  v[b]
    __shared__ unsigned int msk[64][4];      // 1KB:   activity bitmasks per j
    __shared__ __half2 qw2[16][32];          // 2KB:   0.5*q per warp
    __shared__ unsigned char slist[16][SS];  // 2KB
    __shared__ __half awb[16][2*SS];         // 8KB:   aw interleaved (j0,j1)
    __shared__ __half2 wes2[32];             // we half2
    __shared__ float wesf[DD];               // we f32

    const float2* kb = (const float2*)(g_k + b*SS*DD);
    const float2* vb = (const float2*)(g_v + b*SS*DD);
    for (int t = tid; t < SS*32; t += 512) {
        int row = t >> 5, dp = t & 31;
        float2 kf = kb[t];
        ks2[row*33 + dp] = __floats2half2_rn(0.5f*kf.x, 0.5f*kf.y);
        float2 vf = vb[t];
        vs2[t] = __floats2half2_rn(vf.x, vf.y);
    }
    if (tid < 32) {
        float2 wf = *(const float2*)&we[tid*2];
        wes2[tid] = __floats2half2_rn(wf.x, wf.y);
    }
    if (tid >= 64 && tid < 128) wesf[tid - 64] = we[tid - 64];
    if (tid >= 128 && tid < 384) {
        int t = tid - 128;
        int jl = t >> 2, ii = t & 3;
        const int* Ac = A + (b*SS + ii*32)*SS + jh*64 + jl;
        unsigned m = 0;
#pragma unroll
        for (int l = 0; l < 32; l++) m |= (unsigned)(Ac[l*SS] == 1) << l;
        msk[jl][ii] = m;
    }
    __syncthreads();

    float e0;
    {
        float s = 0.f;
#pragma unroll
        for (int c = 0; c < DD; c++) s += wesf[c];
        e0 = 0.5f * s;                       // logit of an inactive edge
    }
    float2 pr = *(const float2*)&prelu2[lane*2];

    for (int pair = 0; pair < 2; pair++) {
        // ---- phase A: logits + softmax for j(par=0) and j(par=1) ----
        for (int par = 0; par < 2; par++) {
            int jl = (w << 2) + (pair << 1) + par;
            int j  = (jh << 6) + jl;
            {
                float2 qf = *(const float2*)&g_q[(b*SS + j)*DD + lane*2];
                qw2[w][lane] = __floats2half2_rn(0.5f*qf.x, 0.5f*qf.y);
            }
            __syncwarp();

            // compaction from bitmask
            int n = 0;
#pragma unroll
            for (int ii = 0; ii < 4; ii++) {
                unsigned m = msk[jl][ii];
                if ((m >> lane) & 1u)
                    slist[w][n + __popc(m & ((1u << lane) - 1u))] =
                        (unsigned char)(ii*32 + lane);
                n += __popc(m);
            }
            __syncwarp();
            int nIter = (n + 31) >> 5;

            float sreg[4];
#pragma unroll
            for (int it = 0; it < 4; it++) {
                sreg[it] = -1e30f;
                if (it < nIter) {
                    int idx = (it << 5) + lane;
                    bool val = idx < n;
                    int i = val ? (int)slist[w][idx] : lane;
                    const __half2* kr = &ks2[i*33];
                    float s0 = 0.f, s1 = 0.f;
#pragma unroll
                    for (int c8 = 0; c8 < 4; c8++) {
                        __half2 sacc = __float2half2_rn(0.f);
#pragma unroll
                        for (int dd = c8*8; dd < c8*8 + 8; dd++) {
                            __half2 z = __hadd2(kr[dd], qw2[w][dd]);
                            sacc = __hfma2(wes2[dd], tanh2_fast(z), sacc);
                        }
                        float2 f = __half22float2(sacc);
                        s0 += f.x; s1 += f.y;
                    }
                    if (val) sreg[it] = fmaf(0.5f, s0 + s1, e0);
                }
            }

            float mx = e0;
#pragma unroll
            for (int it = 0; it < 4; it++)
                if (it < nIter) mx = fmaxf(mx, warp_max(sreg[it]));
            float sum = (float)(SS - n) * __expf(e0 - mx);
            float preg[4];
#pragma unroll
            for (int it = 0; it < 4; it++)
                if (it < nIter) { preg[it] = __expf(sreg[it] - mx); sum += warp_sum(preg[it]); }
            float inv = __fdividef(1.f, sum);
            float a0 = __expf(e0 - mx) * inv;

            // dense fill with a0, then scatter active weights
            __half ha0 = __float2half(a0);
#pragma unroll
            for (int k2 = 0; k2 < 4; k2++)
                awb[w][2*(lane + 32*k2) + par] = ha0;
            __syncwarp();
#pragma unroll
            for (int it = 0; it < 4; it++)
                if (it < nIter) {
                    int idx = (it << 5) + lane;
                    if (idx < n)
                        awb[w][2*(int)slist[w][idx] + par] = __float2half(preg[it]*inv);
                }
            __syncwarp();
        }

        // ---- phase B: h2 for the two j's, v shared across both ----
        int j0 = (jh << 6) + (w << 2) + (pair << 1), j1 = j0 + 1;
        float x0 = 0.f, y0 = 0.f, x1 = 0.f, y1 = 0.f;
#pragma unroll 8
        for (int i = 0; i < SS; i++) {
            float2 vf = __half22float2(vs2[i*32 + lane]);
            __half2 aw2 = *(__half2*)&awb[w][2*i];
            float2 af = __half22float2(aw2);
            x0 = fmaf(af.x, vf.x, x0); y0 = fmaf(af.x, vf.y, y0);
            x1 = fmaf(af.y, vf.x, x1); y1 = fmaf(af.y, vf.y, y1);
        }
        float2 o0, o1;
        o0.x = x0 >= 0.f ? x0 : pr.x*x0;  o0.y = y0 >= 0.f ? y0 : pr.y*y0;
        o1.x = x1 >= 0.f ? x1 : pr.x*x1;  o1.y = y1 >= 0.f ? y1 : pr.y*y1;
        *(float2*)&g_h2[(b*SS + j0)*DD + lane*2] = o0;
        *(float2*)&g_h2[(b*SS + j1)*DD + lane*2] = o1;
        __syncwarp();
    }
}

// ===== kernel 4: readout + session representation ==========================
// grid BB, 512 threads
__global__ void __launch_bounds__(512) k_readout(
        const int* __restrict__ last_nodes,
        const float* __restrict__ Wu,  const float* __restrict__ bu,
        const float* __restrict__ Wvr, const float* __restrict__ wer,
        const float* __restrict__ prelu3, const float* __restrict__ W_sr,
        float* __restrict__ out) {
    int b = blockIdx.x, tid = threadIdx.x, lane = tid & 31;
    __shared__ float h2s[SS*DD];             // 32KB
    __shared__ float xlast[DD], xv[DD], eatt[SS], outv[DD];
    __shared__ float red[4];
    __shared__ float epart[SS][2];
    __shared__ float psum2[8][DD];

    const float4* hb4 = (const float4*)(g_h2 + b*SS*DD);
    float4* h4 = (float4*)h2s;
    for (int t = tid; t < SS*DD/4; t += 512) h4[t] = hb4[t];
    __syncthreads();

    int ln = last_nodes[b];
    if (tid < DD) xlast[tid] = h2s[ln*DD + tid];
    __syncthreads();
    if (tid < DD) {
        float a = 0.f;
#pragma unroll
        for (int c = 0; c < DD; c++) a = fmaf(xlast[c], Wvr[c*DD + tid], a);
        xv[tid] = a;
    }
    __syncthreads();

    // eatt[s] = sum_d wer[d]*sigmoid(h2[s]@Wu[:,d] + bu[d] + xv[d])
    int d = tid & 63, grp = tid >> 6;        // grp 0..7, items s = grp*16 .. +15
    {
        float acc[16];
        float bx = bu[d] + xv[d];
#pragma unroll
        for (int t = 0; t < 16; t++) acc[t] = bx;
        for (int c = 0; c < DD; c++) {
            float wu = Wu[c*DD + d];
#pragma unroll
            for (int t = 0; t < 16; t++)
                acc[t] = fmaf(h2s[(grp*16 + t)*DD + c], wu, acc[t]);
        }
        float wr = wer[d];
        int halfd = (tid >> 5) & 1;
#pragma unroll
        for (int t = 0; t < 16; t++) {
            float val = wr * fast_sigmoid(acc[t]);
            val = warp_sum(val);
            if (lane == 0) epart[grp*16 + t][halfd] = val;
        }
    }
    __syncthreads();
    if (tid < SS) eatt[tid] = epart[tid][0] + epart[tid][1];
    __syncthreads();

    // softmax over s
    float alpha;
    {
        float v = (tid < SS) ? eatt[tid] : -1e30f;
        v = warp_max(v);
        if ((tid & 31) == 0 && tid < SS) red[tid >> 5] = v;
        __syncthreads();
        float mx = fmaxf(fmaxf(red[0], red[1]), fmaxf(red[2], red[3]));
        float ex = (tid < SS) ? __expf(eatt[tid] - mx) : 0.f;
        __syncthreads();
        float sv = warp_sum(ex);
        if ((tid & 31) == 0 && tid < SS) red[tid >> 5] = sv;
        __syncthreads();
        float tot = red[0] + red[1] + red[2] + red[3];
        alpha = ex * __fdividef(1.f, tot);
    }
    __syncthreads();
    if (tid < SS) eatt[tid] = alpha;
    __syncthreads();

    // out[d] = prelu3( sum_s alpha[s]*h2[s][d] )
    {
        float acc = 0.f;
#pragma unroll
        for (int t = 0; t < 16; t++) {
            int s = grp*16 + t;
            acc = fmaf(eatt[s], h2s[s*DD + d], acc);
        }
        psum2[grp][d] = acc;
    }
    __syncthreads();
    if (tid < DD) {
        float sm = 0.f;
#pragma unroll
        for (int g = 0; g < 8; g++) sm += psum2[g][tid];
        float a = prelu3[tid];
        outv[tid] = sm >= 0.f ? sm : a * sm;
    }
    __syncthreads();
    if (tid < DD) {
        float a = 0.f;
#pragma unroll
        for (int c = 0; c < DD; c++) {
            a = fmaf(outv[c],  W_sr[c*DD + tid], a);
            a = fmaf(xlast[c], W_sr[(DD + c)*DD + tid], a);
        }
        out[b*DD + tid] = a;
    }
}

extern "C" void kernel_launch(void* const* d_in, const int* in_sizes, int n_in,
                              void* d_out, int out_size) {
    const int*   items      = (const int*)  d_in[0];
    const int*   A          = (const int*)  d_in[1];
    const int*   eo         = (const int*)  d_in[2];
    const int*   last_nodes = (const int*)  d_in[3];
    // d_in[4] = mask (all true)
    const float* emb        = (const float*)d_in[5];
    const float* W_self     = (const float*)d_in[6];
    const float* W_neigh    = (const float*)d_in[7];
    const float* prelu1     = (const float*)d_in[8];
    const float* Wq         = (const float*)d_in[9];
    const float* bq         = (const float*)d_in[10];
    const float* Wk         = (const float*)d_in[11];
    const float* Wv         = (const float*)d_in[12];
    const float* we         = (const float*)d_in[13];
    const float* prelu2     = (const float*)d_in[14];
    const float* Wu         = (const float*)d_in[15];
    const float* bu         = (const float*)d_in[16];
    const float* Wvr        = (const float*)d_in[17];
    const float* wer        = (const float*)d_in[18];
    const float* prelu3     = (const float*)d_in[19];
    const float* W_sr       = (const float*)d_in[20];
    float* out = (float*)d_out;

    k_gather<<<(BS * DD) / 256, 256>>>(items, emb);
    k_eopa<<<dim3(4, BB), 256>>>(A, eo, W_self, W_neigh, prelu1, Wq, bq, Wk, Wv);
    k_attn<<<dim3(2, BB), 512>>>(A, we, prelu2);
    k_readout<<<BB, 512>>>(last_nodes, Wu, bu, Wvr, wer, prelu3, W_sr, out);
}

// round 11
// speedup vs baseline: 1.3165x; 1.0007x over previous
#include <cuda_runtime.h>
#include <cuda_fp16.h>

#define BB 64
#define SS 128
#define DD 64
#define BS (BB*SS)

// -------- scratch (no allocations allowed) --------
__device__ __align__(16) float g_x [BS*DD];
__device__ __align__(16) float g_q [BS*DD];
__device__ __align__(16) float g_k [BS*DD];
__device__ __align__(16) float g_v [BS*DD];
__device__ __align__(16) float g_h2[BS*DD];
__device__ float g_eatt[BS];

__device__ __forceinline__ float fast_sigmoid(float z) {
    float t;
    asm("tanh.approx.f32 %0, %1;" : "=f"(t) : "f"(0.5f * z));
    return fmaf(0.5f, t, 0.5f);
}
__device__ __forceinline__ __half2 tanh2_fast(__half2 z) {
    unsigned zu = *reinterpret_cast<unsigned*>(&z), tu;
    asm("tanh.approx.f16x2 %0, %1;" : "=r"(tu) : "r"(zu));
    return *reinterpret_cast<__half2*>(&tu);
}
__device__ __forceinline__ float warp_max(float v) {
#pragma unroll
    for (int o = 16; o; o >>= 1) v = fmaxf(v, __shfl_xor_sync(0xffffffffu, v, o));
    return v;
}
__device__ __forceinline__ float warp_sum(float v) {
#pragma unroll
    for (int o = 16; o; o >>= 1) v += __shfl_xor_sync(0xffffffffu, v, o);
    return v;
}

// -------- kernel 1: x = emb[items] --------
__global__ void k_gather(const int* __restrict__ items, const float* __restrict__ emb) {
    int idx = blockIdx.x * blockDim.x + threadIdx.x;
    int bs = idx >> 6, d = idx & 63;
    g_x[idx] = emb[items[bs] * DD + d];
}

// -------- kernel 2: EOPA max + h = prelu(x@Ws + nm@Wn)  +  fused q/k/v --------
// grid (4, BB), 256 threads; block handles 32 rows i = ih*32 .. +31
__global__ void __launch_bounds__(256) k_eopa(
        const int* __restrict__ A, const int* __restrict__ eo,
        const float* __restrict__ Ws, const float* __restrict__ Wn,
        const float* __restrict__ p1,
        const float* __restrict__ Wq, const float* __restrict__ bq,
        const float* __restrict__ Wk, const float* __restrict__ Wv) {
    int b = blockIdx.y, ih = blockIdx.x;
    int tid = threadIdx.x;
    __shared__ float xs[SS*DD];              // 32KB: x[b]
    __shared__ unsigned char cnd[SS*32];     // 4KB: cond[j][i_local]
    __shared__ float buf[32*DD];             // 8KB: nms, then hs

    const float4* xb4 = (const float4*)(g_x + b*SS*DD);
    float4* xs4 = (float4*)xs;
    for (int t = tid; t < SS*DD/4; t += 256) xs4[t] = xb4[t];

    const int* eob = eo + b*SS*SS;
    const int* Ab  = A  + b*SS*SS;
    for (int t = tid; t < SS*32; t += 256) {
        int j = t >> 5, il = t & 31;
        int e = eob[j*SS + ih*32 + il];
        cnd[t] = (Ab[j*SS + e] == 1);
    }
    __syncthreads();

    int d = tid & 63, grp = tid >> 6;        // grp 0..3, items i_local = grp*8 + t
    float m[8];
#pragma unroll
    for (int t = 0; t < 8; t++) m[t] = -1e30f;
    for (int j = 0; j < SS; j++) {
        float xv = xs[j*DD + d];
#pragma unroll
        for (int t = 0; t < 8; t++) {
            bool c = cnd[j*32 + grp*8 + t] != 0;
            m[t] = fmaxf(m[t], c ? xv : 0.f);
        }
    }
#pragma unroll
    for (int t = 0; t < 8; t++) buf[(grp*8+t)*DD + d] = m[t];
    __syncthreads();

    float acc[8];
#pragma unroll
    for (int t = 0; t < 8; t++) acc[t] = 0.f;
    for (int c = 0; c < DD; c++) {
        float ws = Ws[c*DD + d], wn = Wn[c*DD + d];
#pragma unroll
        for (int t = 0; t < 8; t++) {
            int il = grp*8 + t;
            acc[t] = fmaf(xs[(ih*32+il)*DD + c], ws, acc[t]);
            acc[t] = fmaf(buf[il*DD + c], wn, acc[t]);
        }
    }
    float a1 = p1[d];
#pragma unroll
    for (int t = 0; t < 8; t++) { float v = acc[t]; acc[t] = v >= 0.f ? v : a1*v; }
    __syncthreads();                          // all nms reads done
#pragma unroll
    for (int t = 0; t < 8; t++) buf[(grp*8+t)*DD + d] = acc[t];   // hs
    __syncthreads();

    // fused q/k/v projection on the 32 rows
    float aq[8], ak[8], av[8];
    float bqd = bq[d];
#pragma unroll
    for (int t = 0; t < 8; t++) { aq[t] = bqd; ak[t] = 0.f; av[t] = 0.f; }
    for (int c = 0; c < DD; c++) {
        float wq = Wq[c*DD + d], wk = Wk[c*DD + d], wv = Wv[c*DD + d];
#pragma unroll
        for (int t = 0; t < 8; t++) {
            float hv = buf[(grp*8+t)*DD + c];
            aq[t] = fmaf(hv, wq, aq[t]);
            ak[t] = fmaf(hv, wk, ak[t]);
            av[t] = fmaf(hv, wv, av[t]);
        }
    }
#pragma unroll
    for (int t = 0; t < 8; t++) {
        int gi = (b*SS + ih*32 + grp*8 + t)*DD + d;
        g_q[gi] = aq[t];
        g_k[gi] = ak[t];
        g_v[gi] = av[t];
    }
}

// ===== kernel 3: fused attention (logits + softmax + a@v) ==================
// grid (2, BB), 512 threads (16 warps); warp w handles j_local = w*4 .. +3
__global__ void __launch_bounds__(512) k_attn(const int* __restrict__ A,
                                              const float* __restrict__ we,
                                              const float* __restrict__ prelu2) {
    int b = blockIdx.y, jh = blockIdx.x;
    int tid = threadIdx.x, w = tid >> 5, lane = tid & 31;
    __shared__ __half2 ks2[SS*33];           // 16.9KB: 0.5*k[b], pad 33
    __shared__ __half2 vs2[SS*32];           // 16KB:  v[b]
    __shared__ unsigned int msk[64][4];      // 1KB:   activity bitmasks per j
    __shared__ __half2 qw2[16][32];          // 2KB:   0.5*q per warp
    __shared__ unsigned char slist[16][SS];  // 2KB
    __shared__ __half awb[16][2*SS];         // 8KB:   aw interleaved (j0,j1)
    __shared__ __half2 wes2[32];             // we half2
    __shared__ float wesf[DD];               // we f32

    const float2* kb = (const float2*)(g_k + b*SS*DD);
    const float2* vb = (const float2*)(g_v + b*SS*DD);
    for (int t = tid; t < SS*32; t += 512) {
        int row = t >> 5, dp = t & 31;
        float2 kf = kb[t];
        ks2[row*33 + dp] = __floats2half2_rn(0.5f*kf.x, 0.5f*kf.y);
        float2 vf = vb[t];
        vs2[t] = __floats2half2_rn(vf.x, vf.y);
    }
    if (tid < 32) {
        float2 wf = *(const float2*)&we[tid*2];
        wes2[tid] = __floats2half2_rn(wf.x, wf.y);
    }
    if (tid >= 64 && tid < 128) wesf[tid - 64] = we[tid - 64];
    if (tid >= 128 && tid < 384) {
        int t = tid - 128;
        int jl = t >> 2, ii = t & 3;
        const int* Ac = A + (b*SS + ii*32)*SS + jh*64 + jl;
        unsigned m = 0;
#pragma unroll
        for (int l = 0; l < 32; l++) m |= (unsigned)(Ac[l*SS] == 1) << l;
        msk[jl][ii] = m;
    }
    __syncthreads();

    float e0;
    {
        float s = 0.f;
#pragma unroll
        for (int c = 0; c < DD; c++) s += wesf[c];
        e0 = 0.5f * s;                       // logit of an inactive edge
    }
    float2 pr = *(const float2*)&prelu2[lane*2];

    for (int pair = 0; pair < 2; pair++) {
        // ---- phase A: logits + softmax for j(par=0) and j(par=1) ----
        for (int par = 0; par < 2; par++) {
            int jl = (w << 2) + (pair << 1) + par;
            int j  = (jh << 6) + jl;
            {
                float2 qf = *(const float2*)&g_q[(b*SS + j)*DD + lane*2];
                qw2[w][lane] = __floats2half2_rn(0.5f*qf.x, 0.5f*qf.y);
            }
            __syncwarp();

            // compaction from bitmask
            int n = 0;
#pragma unroll
            for (int ii = 0; ii < 4; ii++) {
                unsigned m = msk[jl][ii];
                if ((m >> lane) & 1u)
                    slist[w][n + __popc(m & ((1u << lane) - 1u))] =
                        (unsigned char)(ii*32 + lane);
                n += __popc(m);
            }
            __syncwarp();
            int nIter = (n + 31) >> 5;

            float sreg[4];
#pragma unroll
            for (int it = 0; it < 4; it++) {
                sreg[it] = -1e30f;
                if (it < nIter) {
                    int idx = (it << 5) + lane;
                    bool val = idx < n;
                    int i = val ? (int)slist[w][idx] : lane;
                    const __half2* kr = &ks2[i*33];
                    float s0 = 0.f, s1 = 0.f;
#pragma unroll
                    for (int c8 = 0; c8 < 4; c8++) {
                        __half2 sacc = __float2half2_rn(0.f);
#pragma unroll
                        for (int dd = c8*8; dd < c8*8 + 8; dd++) {
                            __half2 z = __hadd2(kr[dd], qw2[w][dd]);
                            sacc = __hfma2(wes2[dd], tanh2_fast(z), sacc);
                        }
                        float2 f = __half22float2(sacc);
                        s0 += f.x; s1 += f.y;
                    }
                    if (val) sreg[it] = fmaf(0.5f, s0 + s1, e0);
                }
            }

            float mx = e0;
#pragma unroll
            for (int it = 0; it < 4; it++)
                if (it < nIter) mx = fmaxf(mx, warp_max(sreg[it]));
            float sum = (float)(SS - n) * __expf(e0 - mx);
            float preg[4];
#pragma unroll
            for (int it = 0; it < 4; it++)
                if (it < nIter) { preg[it] = __expf(sreg[it] - mx); sum += warp_sum(preg[it]); }
            float inv = __fdividef(1.f, sum);
            float a0 = __expf(e0 - mx) * inv;

            // dense fill with a0, then scatter active weights
            __half ha0 = __float2half(a0);
#pragma unroll
            for (int k2 = 0; k2 < 4; k2++)
                awb[w][2*(lane + 32*k2) + par] = ha0;
            __syncwarp();
#pragma unroll
            for (int it = 0; it < 4; it++)
                if (it < nIter) {
                    int idx = (it << 5) + lane;
                    if (idx < n)
                        awb[w][2*(int)slist[w][idx] + par] = __float2half(preg[it]*inv);
                }
            __syncwarp();
        }

        // ---- phase B: h2 for the two j's, v shared across both ----
        int j0 = (jh << 6) + (w << 2) + (pair << 1), j1 = j0 + 1;
        float x0 = 0.f, y0 = 0.f, x1 = 0.f, y1 = 0.f;
#pragma unroll 8
        for (int i = 0; i < SS; i++) {
            float2 vf = __half22float2(vs2[i*32 + lane]);
            __half2 aw2 = *(__half2*)&awb[w][2*i];
            float2 af = __half22float2(aw2);
            x0 = fmaf(af.x, vf.x, x0); y0 = fmaf(af.x, vf.y, y0);
            x1 = fmaf(af.y, vf.x, x1); y1 = fmaf(af.y, vf.y, y1);
        }
        float2 o0, o1;
        o0.x = x0 >= 0.f ? x0 : pr.x*x0;  o0.y = y0 >= 0.f ? y0 : pr.y*y0;
        o1.x = x1 >= 0.f ? x1 : pr.x*x1;  o1.y = y1 >= 0.f ? y1 : pr.y*y1;
        *(float2*)&g_h2[(b*SS + j0)*DD + lane*2] = o0;
        *(float2*)&g_h2[(b*SS + j1)*DD + lane*2] = o1;
        __syncwarp();
    }
}

// ===== kernel 4a: eatt[s] = sum_d wer[d]*sigmoid(h2[s]@Wu[:,d]+bu[d]+xv[d]) =
// grid (4, BB), 128 threads; block handles 32 s-rows
__global__ void __launch_bounds__(128) k_ro1(
        const int* __restrict__ last_nodes,
        const float* __restrict__ Wu,  const float* __restrict__ bu,
        const float* __restrict__ Wvr, const float* __restrict__ wer) {
    int b = blockIdx.y, sh = blockIdx.x;     // 32 rows s = sh*32 .. +31
    int tid = threadIdx.x, lane = tid & 31;
    __shared__ float h2s[32*DD];             // 8KB
    __shared__ float xlast[DD], xv[DD];
    __shared__ float epart[32][2];

    const float4* hb4 = (const float4*)(g_h2 + (b*SS + sh*32)*DD);
    float4* h4 = (float4*)h2s;
    for (int t = tid; t < 32*DD/4; t += 128) h4[t] = hb4[t];
    int ln = last_nodes[b];
    if (tid < DD) xlast[tid] = g_h2[(b*SS + ln)*DD + tid];
    __syncthreads();
    if (tid < DD) {
        float a = 0.f;
#pragma unroll
        for (int c = 0; c < DD; c++) a = fmaf(xlast[c], Wvr[c*DD + tid], a);
        xv[tid] = a;
    }
    __syncthreads();

    int d = tid & 63, grp = tid >> 6;        // grp 0..1, 16 s each
    float acc[16];
    float bx = bu[d] + xv[d];
#pragma unroll
    for (int t = 0; t < 16; t++) acc[t] = bx;
    for (int c = 0; c < DD; c++) {
        float wu = Wu[c*DD + d];
#pragma unroll
        for (int t = 0; t < 16; t++)
            acc[t] = fmaf(h2s[(grp*16 + t)*DD + c], wu, acc[t]);
    }
    float wr = wer[d];
    int halfd = (tid >> 5) & 1;
#pragma unroll
    for (int t = 0; t < 16; t++) {
        float val = wr * fast_sigmoid(acc[t]);
        val = warp_sum(val);
        if (lane == 0) epart[grp*16 + t][halfd] = val;
    }
    __syncthreads();
    if (tid < 32) g_eatt[b*SS + sh*32 + tid] = epart[tid][0] + epart[tid][1];
}

// ===== kernel 4b: softmax + weighted sum + session representation ==========
// grid BB, 128 threads
__global__ void __launch_bounds__(128) k_ro2(
        const int* __restrict__ last_nodes,
        const float* __restrict__ prelu3, const float* __restrict__ W_sr,
        float* __restrict__ out) {
    int b = blockIdx.x, tid = threadIdx.x, lane = tid & 31;
    __shared__ float eatt[SS], red[4], part[2][DD], xlast[DD], outv[DD];

    float ev = g_eatt[b*SS + tid];
    int ln = last_nodes[b];
    if (tid < DD) xlast[tid] = g_h2[(b*SS + ln)*DD + tid];

    // softmax over 128 values
    float m = warp_max(ev);
    if (lane == 0) red[tid >> 5] = m;
    __syncthreads();
    float mx = fmaxf(fmaxf(red[0], red[1]), fmaxf(red[2], red[3]));
    float ex = __expf(ev - mx);
    __syncthreads();
    float sv = warp_sum(ex);
    if (lane == 0) red[tid >> 5] = sv;
    __syncthreads();
    float tot = red[0] + red[1] + red[2] + red[3];
    eatt[tid] = ex * __fdividef(1.f, tot);
    __syncthreads();

    // out[d] = prelu3( sum_s alpha[s]*h2[s][d] ), h2 from global (L2-hot)
    int half = tid >> 6, d = tid & 63;
    const float* hb = g_h2 + b*SS*DD;
    float acc = 0.f;
#pragma unroll 4
    for (int s = half*64; s < half*64 + 64; s++)
        acc = fmaf(eatt[s], hb[s*DD + d], acc);
    part[half][d] = acc;
    __syncthreads();
    if (tid < DD) {
        float sm = part[0][tid] + part[1][tid];
        float a = prelu3[tid];
        outv[tid] = sm >= 0.f ? sm : a * sm;
    }
    __syncthreads();
    if (tid < DD) {
        float a = 0.f;
#pragma unroll
        for (int c = 0; c < DD; c++) {
            a = fmaf(outv[c],  W_sr[c*DD + tid], a);
            a = fmaf(xlast[c], W_sr[(DD + c)*DD + tid], a);
        }
        out[b*DD + tid] = a;
    }
}

extern "C" void kernel_launch(void* const* d_in, const int* in_sizes, int n_in,
                              void* d_out, int out_size) {
    const int*   items      = (const int*)  d_in[0];
    const int*   A          = (const int*)  d_in[1];
    const int*   eo         = (const int*)  d_in[2];
    const int*   last_nodes = (const int*)  d_in[3];
    // d_in[4] = mask (all true)
    const float* emb        = (const float*)d_in[5];
    const float* W_self     = (const float*)d_in[6];
    const float* W_neigh    = (const float*)d_in[7];
    const float* prelu1     = (const float*)d_in[8];
    const float* Wq         = (const float*)d_in[9];
    const float* bq         = (const float*)d_in[10];
    const float* Wk         = (const float*)d_in[11];
    const float* Wv         = (const float*)d_in[12];
    const float* we         = (const float*)d_in[13];
    const float* prelu2     = (const float*)d_in[14];
    const float* Wu         = (const float*)d_in[15];
    const float* bu         = (const float*)d_in[16];
    const float* Wvr        = (const float*)d_in[17];
    const float* wer        = (const float*)d_in[18];
    const float* prelu3     = (const float*)d_in[19];
    const float* W_sr       = (const float*)d_in[20];
    float* out = (float*)d_out;

    k_gather<<<(BS * DD) / 256, 256>>>(items, emb);
    k_eopa<<<dim3(4, BB), 256>>>(A, eo, W_self, W_neigh, prelu1, Wq, bq, Wk, Wv);
    k_attn<<<dim3(2, BB), 512>>>(A, we, prelu2);
    k_ro1<<<dim3(4, BB), 128>>>(last_nodes, Wu, bu, Wvr, wer);
    k_ro2<<<BB, 128>>>(last_nodes, prelu3, W_sr, out);
}

// round 12
// speedup vs baseline: 1.4480x; 1.0999x over previous
#include <cuda_runtime.h>
#include <cuda_fp16.h>

#define BB 64
#define SS 128
#define DD 64
#define BS (BB*SS)

// -------- scratch (no allocations allowed) --------
__device__ __align__(16) float g_q [BS*DD];
__device__ __align__(16) float g_k [BS*DD];
__device__ __align__(16) float g_v [BS*DD];
__device__ __align__(16) float g_h2[BS*DD];
__device__ float g_eatt[BS];

__device__ __forceinline__ float fast_sigmoid(float z) {
    float t;
    asm("tanh.approx.f32 %0, %1;" : "=f"(t) : "f"(0.5f * z));
    return fmaf(0.5f, t, 0.5f);
}
__device__ __forceinline__ __half2 tanh2_fast(__half2 z) {
    unsigned zu = *reinterpret_cast<unsigned*>(&z), tu;
    asm("tanh.approx.f16x2 %0, %1;" : "=r"(tu) : "r"(zu));
    return *reinterpret_cast<__half2*>(&tu);
}
__device__ __forceinline__ float warp_max(float v) {
#pragma unroll
    for (int o = 16; o; o >>= 1) v = fmaxf(v, __shfl_xor_sync(0xffffffffu, v, o));
    return v;
}
__device__ __forceinline__ float warp_sum(float v) {
#pragma unroll
    for (int o = 16; o; o >>= 1) v += __shfl_xor_sync(0xffffffffu, v, o);
    return v;
}

// -------- kernel 1: EOPA max + h = prelu(x@Ws + nm@Wn)  +  fused q/k/v ----
// (embedding gather folded into the xs staging; matmuls read smem)
// grid (4, BB), 256 threads; block handles 32 rows i = ih*32 .. +31
__global__ void __launch_bounds__(256) k_eopa(
        const int* __restrict__ items,
        const int* __restrict__ A, const int* __restrict__ eo,
        const float* __restrict__ emb,
        const float* __restrict__ Ws, const float* __restrict__ Wn,
        const float* __restrict__ p1,
        const float* __restrict__ Wq, const float* __restrict__ bq,
        const float* __restrict__ Wk, const float* __restrict__ Wv) {
    int b = blockIdx.y, ih = blockIdx.x;
    int tid = threadIdx.x;
    __shared__ float xs[SS*DD];              // 32KB: x[b] = emb[items[b]]
    __shared__ unsigned char cnd[SS*32];     // 4KB: cond[j][i_local]
    __shared__ float buf[32*DD];             // 8KB: nms, then hs

    // stage x[b] straight from emb (row-contiguous, float4)
    const int* itb = items + b*SS;
    for (int t = tid; t < SS*16; t += 256) {
        int row = t >> 4, q4 = t & 15;
        ((float4*)xs)[row*16 + q4] =
            ((const float4*)(emb + __ldg(&itb[row])*DD))[q4];
    }

    const int* eob = eo + b*SS*SS;
    const int* Ab  = A  + b*SS*SS;
    for (int t = tid; t < SS*32; t += 256) {
        int j = t >> 5, il = t & 31;
        int e = eob[j*SS + ih*32 + il];
        cnd[t] = (Ab[j*SS + e] == 1);
    }
    __syncthreads();

    int d = tid & 63, grp = tid >> 6;        // grp 0..3, items i_local = grp*8 + t
    float m[8];
#pragma unroll
    for (int t = 0; t < 8; t++) m[t] = -1e30f;
    for (int j = 0; j < SS; j++) {
        float xv = xs[j*DD + d];
#pragma unroll
        for (int t = 0; t < 8; t++) {
            bool c = cnd[j*32 + grp*8 + t] != 0;
            m[t] = fmaxf(m[t], c ? xv : 0.f);
        }
    }
#pragma unroll
    for (int t = 0; t < 8; t++) buf[(grp*8+t)*DD + d] = m[t];
    __syncthreads();

    float acc[8];
#pragma unroll
    for (int t = 0; t < 8; t++) acc[t] = 0.f;
    for (int c = 0; c < DD; c++) {
        float ws = Ws[c*DD + d], wn = Wn[c*DD + d];
#pragma unroll
        for (int t = 0; t < 8; t++) {
            int il = grp*8 + t;
            acc[t] = fmaf(xs[(ih*32+il)*DD + c], ws, acc[t]);
            acc[t] = fmaf(buf[il*DD + c], wn, acc[t]);
        }
    }
    float a1 = p1[d];
#pragma unroll
    for (int t = 0; t < 8; t++) { float v = acc[t]; acc[t] = v >= 0.f ? v : a1*v; }
    __syncthreads();                          // all nms reads done
#pragma unroll
    for (int t = 0; t < 8; t++) buf[(grp*8+t)*DD + d] = acc[t];   // hs
    __syncthreads();

    // fused q/k/v projection on the 32 rows
    float aq[8], ak[8], av[8];
    float bqd = bq[d];
#pragma unroll
    for (int t = 0; t < 8; t++) { aq[t] = bqd; ak[t] = 0.f; av[t] = 0.f; }
    for (int c = 0; c < DD; c++) {
        float wq = Wq[c*DD + d], wk = Wk[c*DD + d], wv = Wv[c*DD + d];
#pragma unroll
        for (int t = 0; t < 8; t++) {
            float hv = buf[(grp*8+t)*DD + c];
            aq[t] = fmaf(hv, wq, aq[t]);
            ak[t] = fmaf(hv, wk, ak[t]);
            av[t] = fmaf(hv, wv, av[t]);
        }
    }
#pragma unroll
    for (int t = 0; t < 8; t++) {
        int gi = (b*SS + ih*32 + grp*8 + t)*DD + d;
        g_q[gi] = aq[t];
        g_k[gi] = ak[t];
        g_v[gi] = av[t];
    }
}

// ===== kernel 2: fused attention (logits + softmax + a@v) ==================
// grid (2, BB), 512 threads (16 warps); warp w handles j_local = w*4 .. +3
__global__ void __launch_bounds__(512) k_attn(const int* __restrict__ A,
                                              const float* __restrict__ we,
                                              const float* __restrict__ prelu2) {
    int b = blockIdx.y, jh = blockIdx.x;
    int tid = threadIdx.x, w = tid >> 5, lane = tid & 31;
    __shared__ __half2 ks2[SS*33];           // 16.9KB: 0.5*k[b], pad 33
    __shared__ __half2 vs2[SS*32];           // 16KB:  v[b]
    __shared__ unsigned int msk[64][4];      // 1KB:   activity bitmasks per j
    __shared__ __half2 qw2[16][32];          // 2KB:   0.5*q per warp
    __shared__ unsigned char slist[16][SS];  // 2KB
    __shared__ __half awb[16][2*SS];         // 8KB:   aw interleaved (j0,j1)
    __shared__ __half2 wes2[32];             // we half2
    __shared__ float wesf[DD];               // we f32

    const float2* kb = (const float2*)(g_k + b*SS*DD);
    const float2* vb = (const float2*)(g_v + b*SS*DD);
    for (int t = tid; t < SS*32; t += 512) {
        int row = t >> 5, dp = t & 31;
        float2 kf = kb[t];
        ks2[row*33 + dp] = __floats2half2_rn(0.5f*kf.x, 0.5f*kf.y);
        float2 vf = vb[t];
        vs2[t] = __floats2half2_rn(vf.x, vf.y);
    }
    if (tid < 32) {
        float2 wf = *(const float2*)&we[tid*2];
        wes2[tid] = __floats2half2_rn(wf.x, wf.y);
    }
    if (tid >= 64 && tid < 128) wesf[tid - 64] = we[tid - 64];
    if (tid >= 128 && tid < 384) {
        int t = tid - 128;
        int jl = t >> 2, ii = t & 3;
        const int* Ac = A + (b*SS + ii*32)*SS + jh*64 + jl;
        unsigned m = 0;
#pragma unroll
        for (int l = 0; l < 32; l++) m |= (unsigned)(Ac[l*SS] == 1) << l;
        msk[jl][ii] = m;
    }
    __syncthreads();

    float e0;
    {
        float s = 0.f;
#pragma unroll
        for (int c = 0; c < DD; c++) s += wesf[c];
        e0 = 0.5f * s;                       // logit of an inactive edge
    }
    float2 pr = *(const float2*)&prelu2[lane*2];

    for (int pair = 0; pair < 2; pair++) {
        // ---- phase A: logits + softmax for j(par=0) and j(par=1) ----
        for (int par = 0; par < 2; par++) {
            int jl = (w << 2) + (pair << 1) + par;
            int j  = (jh << 6) + jl;
            {
                float2 qf = *(const float2*)&g_q[(b*SS + j)*DD + lane*2];
                qw2[w][lane] = __floats2half2_rn(0.5f*qf.x, 0.5f*qf.y);
            }
            __syncwarp();

            // compaction from bitmask
            int n = 0;
#pragma unroll
            for (int ii = 0; ii < 4; ii++) {
                unsigned m = msk[jl][ii];
                if ((m >> lane) & 1u)
                    slist[w][n + __popc(m & ((1u << lane) - 1u))] =
                        (unsigned char)(ii*32 + lane);
                n += __popc(m);
            }
            __syncwarp();
            int nIter = (n + 31) >> 5;

            float sreg[4];
#pragma unroll
            for (int it = 0; it < 4; it++) {
                sreg[it] = -1e30f;
                if (it < nIter) {
                    int idx = (it << 5) + lane;
                    bool val = idx < n;
                    int i = val ? (int)slist[w][idx] : lane;
                    const __half2* kr = &ks2[i*33];
                    float s0 = 0.f, s1 = 0.f;
#pragma unroll
                    for (int c8 = 0; c8 < 4; c8++) {
                        __half2 sacc = __float2half2_rn(0.f);
#pragma unroll
                        for (int dd = c8*8; dd < c8*8 + 8; dd++) {
                            __half2 z = __hadd2(kr[dd], qw2[w][dd]);
                            sacc = __hfma2(wes2[dd], tanh2_fast(z), sacc);
                        }
                        float2 f = __half22float2(sacc);
                        s0 += f.x; s1 += f.y;
                    }
                    if (val) sreg[it] = fmaf(0.5f, s0 + s1, e0);
                }
            }

            float mx = e0;
#pragma unroll
            for (int it = 0; it < 4; it++)
                if (it < nIter) mx = fmaxf(mx, warp_max(sreg[it]));
            float sum = (float)(SS - n) * __expf(e0 - mx);
            float preg[4];
#pragma unroll
            for (int it = 0; it < 4; it++)
                if (it < nIter) { preg[it] = __expf(sreg[it] - mx); sum += warp_sum(preg[it]); }
            float inv = __fdividef(1.f, sum);
            float a0 = __expf(e0 - mx) * inv;

            // dense fill with a0, then scatter active weights
            __half ha0 = __float2half(a0);
#pragma unroll
            for (int k2 = 0; k2 < 4; k2++)
                awb[w][2*(lane + 32*k2) + par] = ha0;
            __syncwarp();
#pragma unroll
            for (int it = 0; it < 4; it++)
                if (it < nIter) {
                    int idx = (it << 5) + lane;
                    if (idx < n)
                        awb[w][2*(int)slist[w][idx] + par] = __float2half(preg[it]*inv);
                }
            __syncwarp();
        }

        // ---- phase B: h2 for the two j's, v shared across both ----
        int j0 = (jh << 6) + (w << 2) + (pair << 1), j1 = j0 + 1;
        float x0 = 0.f, y0 = 0.f, x1 = 0.f, y1 = 0.f;
#pragma unroll 8
        for (int i = 0; i < SS; i++) {
            float2 vf = __half22float2(vs2[i*32 + lane]);
            __half2 aw2 = *(__half2*)&awb[w][2*i];
            float2 af = __half22float2(aw2);
            x0 = fmaf(af.x, vf.x, x0); y0 = fmaf(af.x, vf.y, y0);
            x1 = fmaf(af.y, vf.x, x1); y1 = fmaf(af.y, vf.y, y1);
        }
        float2 o0, o1;
        o0.x = x0 >= 0.f ? x0 : pr.x*x0;  o0.y = y0 >= 0.f ? y0 : pr.y*y0;
        o1.x = x1 >= 0.f ? x1 : pr.x*x1;  o1.y = y1 >= 0.f ? y1 : pr.y*y1;
        *(float2*)&g_h2[(b*SS + j0)*DD + lane*2] = o0;
        *(float2*)&g_h2[(b*SS + j1)*DD + lane*2] = o1;
        __syncwarp();
    }
}

// ===== kernel 3a: eatt[s] = sum_d wer[d]*sigmoid(h2[s]@Wu[:,d]+bu[d]+xv[d])
// grid (4, BB), 256 threads (8 warps); warp w owns rows sh*32 + w*4 .. +3;
// lane owns d-pair {2*lane, 2*lane+1}. Wu staged in smem.
__global__ void __launch_bounds__(256) k_ro1(
        const int* __restrict__ last_nodes,
        const float* __restrict__ Wu,  const float* __restrict__ bu,
        const float* __restrict__ Wvr, const float* __restrict__ wer) {
    int b = blockIdx.y, sh = blockIdx.x;
    int tid = threadIdx.x, w = tid >> 5, lane = tid & 31;
    __shared__ float2 wu2[DD*32];            // 16KB: Wu[c][dpair]
    __shared__ float h2s[32*DD];             // 8KB
    __shared__ float xlast[DD], xv[DD];
    __shared__ float eout[32];

    const float2* Wuf2 = (const float2*)Wu;
    for (int t = tid; t < DD*32; t += 256) wu2[t] = Wuf2[t];
    const float4* hb4 = (const float4*)(g_h2 + (b*SS + sh*32)*DD);
    for (int t = tid; t < 32*DD/4; t += 256) ((float4*)h2s)[t] = hb4[t];
    int ln = last_nodes[b];
    if (tid < DD) xlast[tid] = g_h2[(b*SS + ln)*DD + tid];
    __syncthreads();
    if (tid < DD) {
        float a = 0.f;
#pragma unroll
        for (int c = 0; c < DD; c++) a = fmaf(xlast[c], Wvr[c*DD + tid], a);
        xv[tid] = a;
    }
    __syncthreads();

    float bx = bu[2*lane]     + xv[2*lane];
    float by = bu[2*lane + 1] + xv[2*lane + 1];
    float2 acc[4];
#pragma unroll
    for (int r = 0; r < 4; r++) { acc[r].x = bx; acc[r].y = by; }
    const float* hrow = &h2s[(w*4)*DD];
#pragma unroll 16
    for (int c = 0; c < DD; c++) {
        float2 wuc = wu2[c*32 + lane];
#pragma unroll
        for (int r = 0; r < 4; r++) {
            float h = hrow[r*DD + c];
            acc[r].x = fmaf(h, wuc.x, acc[r].x);
            acc[r].y = fmaf(h, wuc.y, acc[r].y);
        }
    }
    float wx = wer[2*lane], wy = wer[2*lane + 1];
#pragma unroll
    for (int r = 0; r < 4; r++) {
        float val = fmaf(wx, fast_sigmoid(acc[r].x), wy * fast_sigmoid(acc[r].y));
        val = warp_sum(val);
        if (lane == 0) eout[w*4 + r] = val;
    }
    __syncthreads();
    if (tid < 32) g_eatt[b*SS + sh*32 + tid] = eout[tid];
}

// ===== kernel 3b: softmax + weighted sum + session representation ==========
// grid BB, 128 threads
__global__ void __launch_bounds__(128) k_ro2(
        const int* __restrict__ last_nodes,
        const float* __restrict__ prelu3, const float* __restrict__ W_sr,
        float* __restrict__ out) {
    int b = blockIdx.x, tid = threadIdx.x, lane = tid & 31;
    __shared__ float eatt[SS], red[4], part[2][DD], xlast[DD], outv[DD];

    float ev = g_eatt[b*SS + tid];
    int ln = last_nodes[b];
    if (tid < DD) xlast[tid] = g_h2[(b*SS + ln)*DD + tid];

    // softmax over 128 values
    float m = warp_max(ev);
    if (lane == 0) red[tid >> 5] = m;
    __syncthreads();
    float mx = fmaxf(fmaxf(red[0], red[1]), fmaxf(red[2], red[3]));
    float ex = __expf(ev - mx);
    __syncthreads();
    float sv = warp_sum(ex);
    if (lane == 0) red[tid >> 5] = sv;
    __syncthreads();
    float tot = red[0] + red[1] + red[2] + red[3];
    eatt[tid] = ex * __fdividef(1.f, tot);
    __syncthreads();

    // out[d] = prelu3( sum_s alpha[s]*h2[s][d] ), h2 from global (L2-hot)
    int half = tid >> 6, d = tid & 63;
    const float* hb = g_h2 + b*SS*DD;
    float acc = 0.f;
#pragma unroll 4
    for (int s = half*64; s < half*64 + 64; s++)
        acc = fmaf(eatt[s], hb[s*DD + d], acc);
    part[half][d] = acc;
    __syncthreads();
    if (tid < DD) {
        float sm = part[0][tid] + part[1][tid];
        float a = prelu3[tid];
        outv[tid] = sm >= 0.f ? sm : a * sm;
    }
    __syncthreads();
    if (tid < DD) {
        float a = 0.f;
#pragma unroll
        for (int c = 0; c < DD; c++) {
            a = fmaf(outv[c],  W_sr[c*DD + tid], a);
            a = fmaf(xlast[c], W_sr[(DD + c)*DD + tid], a);
        }
        out[b*DD + tid] = a;
    }
}

extern "C" void kernel_launch(void* const* d_in, const int* in_sizes, int n_in,
                              void* d_out, int out_size) {
    const int*   items      = (const int*)  d_in[0];
    const int*   A          = (const int*)  d_in[1];
    const int*   eo         = (const int*)  d_in[2];
    const int*   last_nodes = (const int*)  d_in[3];
    // d_in[4] = mask (all true)
    const float* emb        = (const float*)d_in[5];
    const float* W_self     = (const float*)d_in[6];
    const float* W_neigh    = (const float*)d_in[7];
    const float* prelu1     = (const float*)d_in[8];
    const float* Wq         = (const float*)d_in[9];
    const float* bq         = (const float*)d_in[10];
    const float* Wk         = (const float*)d_in[11];
    const float* Wv         = (const float*)d_in[12];
    const float* we         = (const float*)d_in[13];
    const float* prelu2     = (const float*)d_in[14];
    const float* Wu         = (const float*)d_in[15];
    const float* bu         = (const float*)d_in[16];
    const float* Wvr        = (const float*)d_in[17];
    const float* wer        = (const float*)d_in[18];
    const float* prelu3     = (const float*)d_in[19];
    const float* W_sr       = (const float*)d_in[20];
    float* out = (float*)d_out;

    k_eopa<<<dim3(4, BB), 256>>>(items, A, eo, emb, W_self, W_neigh, prelu1,
                                 Wq, bq, Wk, Wv);
    k_attn<<<dim3(2, BB), 512>>>(A, we, prelu2);
    k_ro1<<<dim3(4, BB), 256>>>(last_nodes, Wu, bu, Wvr, wer);
    k_ro2<<<BB, 128>>>(last_nodes, prelu3, W_sr, out);
}

// round 16
// speedup vs baseline: 1.5274x; 1.0548x over previous
#include <cuda_runtime.h>
#include <cuda_fp16.h>

#define BB 64
#define SS 128
#define DD 64
#define BS (BB*SS)

// -------- scratch (no allocations allowed) --------
__device__ __align__(16) float g_q [BS*DD];
__device__ __align__(16) float g_k [BS*DD];
__device__ __align__(16) float g_v [BS*DD];
__device__ __align__(16) float g_h2[BS*DD];

__device__ __forceinline__ float fast_sigmoid(float z) {
    float t;
    asm("tanh.approx.f32 %0, %1;" : "=f"(t) : "f"(0.5f * z));
    return fmaf(0.5f, t, 0.5f);
}
__device__ __forceinline__ __half2 tanh2_fast(__half2 z) {
    unsigned zu = *reinterpret_cast<unsigned*>(&z), tu;
    asm("tanh.approx.f16x2 %0, %1;" : "=r"(tu) : "r"(zu));
    return *reinterpret_cast<__half2*>(&tu);
}
__device__ __forceinline__ float warp_max(float v) {
#pragma unroll
    for (int o = 16; o; o >>= 1) v = fmaxf(v, __shfl_xor_sync(0xffffffffu, v, o));
    return v;
}
__device__ __forceinline__ float warp_sum(float v) {
#pragma unroll
    for (int o = 16; o; o >>= 1) v += __shfl_xor_sync(0xffffffffu, v, o);
    return v;
}

// -------- kernel 1: EOPA max + h = prelu(x@Ws + nm@Wn)  +  fused q/k/v ----
// grid (4, BB), 256 threads; block handles 32 rows i = ih*32 .. +31
__global__ void __launch_bounds__(256) k_eopa(
        const int* __restrict__ items,
        const int* __restrict__ A, const int* __restrict__ eo,
        const float* __restrict__ emb,
        const float* __restrict__ Ws, const float* __restrict__ Wn,
        const float* __restrict__ p1,
        const float* __restrict__ Wq, const float* __restrict__ bq,
        const float* __restrict__ Wk, const float* __restrict__ Wv) {
    int b = blockIdx.y, ih = blockIdx.x;
    int tid = threadIdx.x;
    __shared__ float xs[SS*DD];              // 32KB: x[b] = emb[items[b]]
    __shared__ unsigned char cnd[SS*32];     // 4KB: cond[j][i_local]
    __shared__ float buf[32*DD];             // 8KB: nms, then hs

    // stage x[b] straight from emb (row-contiguous, float4)
    const int* itb = items + b*SS;
    for (int t = tid; t < SS*16; t += 256) {
        int row = t >> 4, q4 = t & 15;
        ((float4*)xs)[row*16 + q4] =
            ((const float4*)(emb + __ldg(&itb[row])*DD))[q4];
    }

    const int* eob = eo + b*SS*SS;
    const int* Ab  = A  + b*SS*SS;
    for (int t = tid; t < SS*32; t += 256) {
        int j = t >> 5, il = t & 31;
        int e = eob[j*SS + ih*32 + il];
        cnd[t] = (Ab[j*SS + e] == 1);
    }
    __syncthreads();

    int d = tid & 63, grp = tid >> 6;        // grp 0..3, items i_local = grp*8 + t
    float m[8];
#pragma unroll
    for (int t = 0; t < 8; t++) m[t] = -1e30f;
    for (int j = 0; j < SS; j++) {
        float xv = xs[j*DD + d];
#pragma unroll
        for (int t = 0; t < 8; t++) {
            bool c = cnd[j*32 + grp*8 + t] != 0;
            m[t] = fmaxf(m[t], c ? xv : 0.f);
        }
    }
#pragma unroll
    for (int t = 0; t < 8; t++) buf[(grp*8+t)*DD + d] = m[t];
    __syncthreads();

    float acc[8];
#pragma unroll
    for (int t = 0; t < 8; t++) acc[t] = 0.f;
    for (int c = 0; c < DD; c++) {
        float ws = Ws[c*DD + d], wn = Wn[c*DD + d];
#pragma unroll
        for (int t = 0; t < 8; t++) {
            int il = grp*8 + t;
            acc[t] = fmaf(xs[(ih*32+il)*DD + c], ws, acc[t]);
            acc[t] = fmaf(buf[il*DD + c], wn, acc[t]);
        }
    }
    float a1 = p1[d];
#pragma unroll
    for (int t = 0; t < 8; t++) { float v = acc[t]; acc[t] = v >= 0.f ? v : a1*v; }
    __syncthreads();                          // all nms reads done
#pragma unroll
    for (int t = 0; t < 8; t++) buf[(grp*8+t)*DD + d] = acc[t];   // hs
    __syncthreads();

    // fused q/k/v projection on the 32 rows
    float aq[8], ak[8], av[8];
    float bqd = bq[d];
#pragma unroll
    for (int t = 0; t < 8; t++) { aq[t] = bqd; ak[t] = 0.f; av[t] = 0.f; }
    for (int c = 0; c < DD; c++) {
        float wq = Wq[c*DD + d], wk = Wk[c*DD + d], wv = Wv[c*DD + d];
#pragma unroll
        for (int t = 0; t < 8; t++) {
            float hv = buf[(grp*8+t)*DD + c];
            aq[t] = fmaf(hv, wq, aq[t]);
            ak[t] = fmaf(hv, wk, ak[t]);
            av[t] = fmaf(hv, wv, av[t]);
        }
    }
#pragma unroll
    for (int t = 0; t < 8; t++) {
        int gi = (b*SS + ih*32 + grp*8 + t)*DD + d;
        g_q[gi] = aq[t];
        g_k[gi] = ak[t];
        g_v[gi] = av[t];
    }
}

// ===== kernel 2: fused attention (logits + softmax + a@v) ==================
// grid (2, BB), 512 threads (16 warps); warp w handles j_local = w*4 .. +3
__global__ void __launch_bounds__(512) k_attn(const int* __restrict__ A,
                                              const float* __restrict__ we,
                                              const float* __restrict__ prelu2) {
    int b = blockIdx.y, jh = blockIdx.x;
    int tid = threadIdx.x, w = tid >> 5, lane = tid & 31;
    __shared__ __half2 ks2[SS*33];           // 16.9KB: 0.5*k[b], pad 33
    __shared__ __half2 vs2[SS*32];           // 16KB:  v[b]
    __shared__ unsigned int msk[64][4];      // 1KB:   activity bitmasks per j
    __shared__ __half2 qw2[16][32];          // 2KB:   0.5*q per warp
    __shared__ unsigned char slist[16][SS];  // 2KB
    __shared__ __half awb[16][2*SS];         // 8KB:   aw interleaved (j0,j1)
    __shared__ __half2 wes2[32];             // we half2
    __shared__ float wesf[DD];               // we f32

    const float2* kb = (const float2*)(g_k + b*SS*DD);
    const float2* vb = (const float2*)(g_v + b*SS*DD);
    for (int t = tid; t < SS*32; t += 512) {
        int row = t >> 5, dp = t & 31;
        float2 kf = kb[t];
        ks2[row*33 + dp] = __floats2half2_rn(0.5f*kf.x, 0.5f*kf.y);
        float2 vf = vb[t];
        vs2[t] = __floats2half2_rn(vf.x, vf.y);
    }
    if (tid < 32) {
        float2 wf = *(const float2*)&we[tid*2];
        wes2[tid] = __floats2half2_rn(wf.x, wf.y);
    }
    if (tid >= 64 && tid < 128) wesf[tid - 64] = we[tid - 64];
    if (tid >= 128 && tid < 384) {
        int t = tid - 128;
        int jl = t >> 2, ii = t & 3;
        const int* Ac = A + (b*SS + ii*32)*SS + jh*64 + jl;
        unsigned m = 0;
#pragma unroll
        for (int l = 0; l < 32; l++) m |= (unsigned)(Ac[l*SS] == 1) << l;
        msk[jl][ii] = m;
    }
    __syncthreads();

    float e0;
    {
        float s = 0.f;
#pragma unroll
        for (int c = 0; c < DD; c++) s += wesf[c];
        e0 = 0.5f * s;                       // logit of an inactive edge
    }
    float2 pr = *(const float2*)&prelu2[lane*2];

    for (int pair = 0; pair < 2; pair++) {
        // ---- phase A: logits + softmax for j(par=0) and j(par=1) ----
        for (int par = 0; par < 2; par++) {
            int jl = (w << 2) + (pair << 1) + par;
            int j  = (jh << 6) + jl;
            {
                float2 qf = *(const float2*)&g_q[(b*SS + j)*DD + lane*2];
                qw2[w][lane] = __floats2half2_rn(0.5f*qf.x, 0.5f*qf.y);
            }
            __syncwarp();

            // compaction from bitmask
            int n = 0;
#pragma unroll
            for (int ii = 0; ii < 4; ii++) {
                unsigned m = msk[jl][ii];
                if ((m >> lane) & 1u)
                    slist[w][n + __popc(m & ((1u << lane) - 1u))] =
                        (unsigned char)(ii*32 + lane);
                n += __popc(m);
            }
            __syncwarp();
            int nIter = (n + 31) >> 5;

            float sreg[4];
#pragma unroll
            for (int it = 0; it < 4; it++) {
                sreg[it] = -1e30f;
                if (it < nIter) {
                    int idx = (it << 5) + lane;
                    bool val = idx < n;
                    int i = val ? (int)slist[w][idx] : lane;
                    const __half2* kr = &ks2[i*33];
                    float s0 = 0.f, s1 = 0.f;
#pragma unroll
                    for (int c8 = 0; c8 < 4; c8++) {
                        __half2 sacc = __float2half2_rn(0.f);
#pragma unroll
                        for (int dd = c8*8; dd < c8*8 + 8; dd++) {
                            __half2 z = __hadd2(kr[dd], qw2[w][dd]);
                            sacc = __hfma2(wes2[dd], tanh2_fast(z), sacc);
                        }
                        float2 f = __half22float2(sacc);
                        s0 += f.x; s1 += f.y;
                    }
                    if (val) sreg[it] = fmaf(0.5f, s0 + s1, e0);
                }
            }

            float mx = e0;
#pragma unroll
            for (int it = 0; it < 4; it++)
                if (it < nIter) mx = fmaxf(mx, warp_max(sreg[it]));
            float sum = (float)(SS - n) * __expf(e0 - mx);
            float preg[4];
#pragma unroll
            for (int it = 0; it < 4; it++)
                if (it < nIter) { preg[it] = __expf(sreg[it] - mx); sum += warp_sum(preg[it]); }
            float inv = __fdividef(1.f, sum);
            float a0 = __expf(e0 - mx) * inv;

            // dense fill with a0, then scatter active weights
            __half ha0 = __float2half(a0);
#pragma unroll
            for (int k2 = 0; k2 < 4; k2++)
                awb[w][2*(lane + 32*k2) + par] = ha0;
            __syncwarp();
#pragma unroll
            for (int it = 0; it < 4; it++)
                if (it < nIter) {
                    int idx = (it << 5) + lane;
                    if (idx < n)
                        awb[w][2*(int)slist[w][idx] + par] = __float2half(preg[it]*inv);
                }
            __syncwarp();
        }

        // ---- phase B: h2 for the two j's, v shared across both ----
        int j0 = (jh << 6) + (w << 2) + (pair << 1), j1 = j0 + 1;
        float x0 = 0.f, y0 = 0.f, x1 = 0.f, y1 = 0.f;
#pragma unroll 8
        for (int i = 0; i < SS; i++) {
            float2 vf = __half22float2(vs2[i*32 + lane]);
            __half2 aw2 = *(__half2*)&awb[w][2*i];
            float2 af = __half22float2(aw2);
            x0 = fmaf(af.x, vf.x, x0); y0 = fmaf(af.x, vf.y, y0);
            x1 = fmaf(af.y, vf.x, x1); y1 = fmaf(af.y, vf.y, y1);
        }
        float2 o0, o1;
        o0.x = x0 >= 0.f ? x0 : pr.x*x0;  o0.y = y0 >= 0.f ? y0 : pr.y*y0;
        o1.x = x1 >= 0.f ? x1 : pr.x*x1;  o1.y = y1 >= 0.f ? y1 : pr.y*y1;
        *(float2*)&g_h2[(b*SS + j0)*DD + lane*2] = o0;
        *(float2*)&g_h2[(b*SS + j1)*DD + lane*2] = o1;
        __syncwarp();
    }
}

// ===== kernel 3: full readout per b (eatt + softmax + sum + W_sr) ==========
// grid BB, 512 threads (16 warps); warp w owns s-rows w*8 .. +7 for eatt;
// lane owns d-pair {2*lane, 2*lane+1}. h2[b] and Wu staged in smem.
__global__ void __launch_bounds__(512) k_ro(
        const int* __restrict__ last_nodes,
        const float* __restrict__ Wu,  const float* __restrict__ bu,
        const float* __restrict__ Wvr, const float* __restrict__ wer,
        const float* __restrict__ prelu3, const float* __restrict__ W_sr,
        float* __restrict__ out) {
    int b = blockIdx.x;
    int tid = threadIdx.x, w = tid >> 5, lane = tid & 31;
    __shared__ float h2s[SS*DD];             // 32KB
    __shared__ float2 wu2[DD*32];            // 16KB: Wu[c][dpair]
    __shared__ float xlast[DD], xv[DD], eatt[SS], outv[DD];
    __shared__ float red[4];
    __shared__ float psum[8][DD];

    const float4* hb4 = (const float4*)(g_h2 + b*SS*DD);
    for (int t = tid; t < SS*DD/4; t += 512) ((float4*)h2s)[t] = hb4[t];
    const float2* Wuf2 = (const float2*)Wu;
    for (int t = tid; t < DD*32; t += 512) wu2[t] = Wuf2[t];
    int ln = last_nodes[b];
    __syncthreads();
    if (tid < DD) xlast[tid] = h2s[ln*DD + tid];
    __syncthreads();
    if (tid < DD) {
        float a = 0.f;
#pragma unroll
        for (int c = 0; c < DD; c++) a = fmaf(xlast[c], Wvr[c*DD + tid], a);
        xv[tid] = a;
    }
    __syncthreads();

    // ---- eatt: warp w owns rows w*8 .. +7, lane owns d-pair ----
    {
        float bx = bu[2*lane]     + xv[2*lane];
        float by = bu[2*lane + 1] + xv[2*lane + 1];
        float2 acc[8];
#pragma unroll
        for (int r = 0; r < 8; r++) { acc[r].x = bx; acc[r].y = by; }
        const float* hrow = &h2s[(w*8)*DD];
#pragma unroll 16
        for (int c = 0; c < DD; c++) {
            float2 wuc = wu2[c*32 + lane];
#pragma unroll
            for (int r = 0; r < 8; r++) {
                float h = hrow[r*DD + c];
                acc[r].x = fmaf(h, wuc.x, acc[r].x);
                acc[r].y = fmaf(h, wuc.y, acc[r].y);
            }
        }
        float wx = wer[2*lane], wy = wer[2*lane + 1];
#pragma unroll
        for (int r = 0; r < 8; r++) {
            float val = fmaf(wx, fast_sigmoid(acc[r].x), wy * fast_sigmoid(acc[r].y));
            val = warp_sum(val);
            if (lane == 0) eatt[w*8 + r] = val;
        }
    }
    __syncthreads();

    // ---- softmax over 128 values (threads 0..127 carry; all hit barriers) --
    {
        float ev = (tid < SS) ? eatt[tid] : -1e30f;
        float m = warp_max(ev);
        if (lane == 0 && tid < SS) red[tid >> 5] = m;
        __syncthreads();
        float mx = fmaxf(fmaxf(red[0], red[1]), fmaxf(red[2], red[3]));
        float ex = (tid < SS) ? __expf(ev - mx) : 0.f;
        __syncthreads();
        float sv = warp_sum(ex);
        if (lane == 0 && tid < SS) red[tid >> 5] = sv;
        __syncthreads();
        float tot = red[0] + red[1] + red[2] + red[3];
        if (tid < SS) eatt[tid] = ex * __fdividef(1.f, tot);
    }
    __syncthreads();

    // ---- out[d] = prelu3( sum_s alpha[s]*h2s[s][d] ) ----
    {
        int d = tid & 63, grp = tid >> 6;    // 8 groups of 16 s
        float acc = 0.f;
#pragma unroll
        for (int t = 0; t < 16; t++) {
            int s = grp*16 + t;
            acc = fmaf(eatt[s], h2s[s*DD + d], acc);
        }
        psum[grp][d] = acc;
    }
    __syncthreads();
    if (tid < DD) {
        float sm = 0.f;
#pragma unroll
        for (int g = 0; g < 8; g++) sm += psum[g][tid];
        float a = prelu3[tid];
        outv[tid] = sm >= 0.f ? sm : a * sm;
    }
    __syncthreads();
    if (tid < DD) {
        float a = 0.f;
#pragma unroll
        for (int c = 0; c < DD; c++) {
            a = fmaf(outv[c],  W_sr[c*DD + tid], a);
            a = fmaf(xlast[c], W_sr[(DD + c)*DD + tid], a);
        }
        out[b*DD + tid] = a;
    }
}

extern "C" void kernel_launch(void* const* d_in, const int* in_sizes, int n_in,
                              void* d_out, int out_size) {
    const int*   items      = (const int*)  d_in[0];
    const int*   A          = (const int*)  d_in[1];
    const int*   eo         = (const int*)  d_in[2];
    const int*   last_nodes = (const int*)  d_in[3];
    // d_in[4] = mask (all true)
    const float* emb        = (const float*)d_in[5];
    const float* W_self     = (const float*)d_in[6];
    const float* W_neigh    = (const float*)d_in[7];
    const float* prelu1     = (const float*)d_in[8];
    const float* Wq         = (const float*)d_in[9];
    const float* bq         = (const float*)d_in[10];
    const float* Wk         = (const float*)d_in[11];
    const float* Wv         = (const float*)d_in[12];
    const float* we         = (const float*)d_in[13];
    const float* prelu2     = (const float*)d_in[14];
    const float* Wu         = (const float*)d_in[15];
    const float* bu         = (const float*)d_in[16];
    const float* Wvr        = (const float*)d_in[17];
    const float* wer        = (const float*)d_in[18];
    const float* prelu3     = (const float*)d_in[19];
    const float* W_sr       = (const float*)d_in[20];
    float* out = (float*)d_out;

    k_eopa<<<dim3(4, BB), 256>>>(items, A, eo, emb, W_self, W_neigh, prelu1,
                                 Wq, bq, Wk, Wv);
    k_attn<<<dim3(2, BB), 512>>>(A, we, prelu2);
    k_ro<<<BB, 512>>>(last_nodes, Wu, bu, Wvr, wer, prelu3, W_sr, out);
}

// round 17
// speedup vs baseline: 1.7345x; 1.1356x over previous
#include <cuda_runtime.h>
#include <cuda_fp16.h>

#define BB 64
#define SS 128
#define DD 64
#define BS (BB*SS)
#define ROWS 16

// -------- scratch (no allocations allowed) --------
__device__ __align__(16) float g_q [BS*DD];
__device__ __align__(16) float g_k [BS*DD];
__device__ __align__(16) float g_v [BS*DD];
__device__ __align__(16) float g_h2[BS*DD];

__device__ __forceinline__ float fast_sigmoid(float z) {
    float t;
    asm("tanh.approx.f32 %0, %1;" : "=f"(t) : "f"(0.5f * z));
    return fmaf(0.5f, t, 0.5f);
}
__device__ __forceinline__ __half2 tanh2_fast(__half2 z) {
    unsigned zu = *reinterpret_cast<unsigned*>(&z), tu;
    asm("tanh.approx.f16x2 %0, %1;" : "=r"(tu) : "r"(zu));
    return *reinterpret_cast<__half2*>(&tu);
}
__device__ __forceinline__ float warp_max(float v) {
#pragma unroll
    for (int o = 16; o; o >>= 1) v = fmaxf(v, __shfl_xor_sync(0xffffffffu, v, o));
    return v;
}
__device__ __forceinline__ float warp_sum(float v) {
#pragma unroll
    for (int o = 16; o; o >>= 1) v += __shfl_xor_sync(0xffffffffu, v, o);
    return v;
}

// -------- kernel 1: EOPA max + h = prelu(x@Ws + nm@Wn)  +  fused q/k/v ----
// grid (8, BB), 256 threads; block handles ROWS=16 rows i = ih*16 .. +15
__global__ void __launch_bounds__(256) k_eopa(
        const int* __restrict__ items,
        const int* __restrict__ A, const int* __restrict__ eo,
        const float* __restrict__ emb,
        const float* __restrict__ Ws, const float* __restrict__ Wn,
        const float* __restrict__ p1,
        const float* __restrict__ Wq, const float* __restrict__ bq,
        const float* __restrict__ Wk, const float* __restrict__ Wv) {
    int b = blockIdx.y, ih = blockIdx.x;
    int tid = threadIdx.x;
    __shared__ __half2 xs2[SS*32];           // 16KB: x[b] as half2 (all 128 rows)
    __shared__ unsigned char cnd[SS*ROWS];   // 2KB: cond[j][i_local]
    __shared__ float nm[ROWS*DD];            // 4KB: neighbor-max
    __shared__ float hs[ROWS*DD];            // 4KB: h
    __shared__ int itm[SS];

    if (tid < SS) itm[tid] = items[b*SS + tid];
    __syncthreads();

    // stage x[b] as half2 straight from emb
    for (int t = tid; t < SS*16; t += 256) {
        int row = t >> 4, q4 = t & 15;
        float4 v = ((const float4*)(emb + itm[row]*DD))[q4];
        xs2[row*32 + q4*2]     = __floats2half2_rn(v.x, v.y);
        xs2[row*32 + q4*2 + 1] = __floats2half2_rn(v.z, v.w);
    }

    // cond[j][il] = (A[b, j, eo[b,j, ih*16+il]] == 1)
    const int* eob = eo + b*SS*SS + ih*ROWS;
    const int* Ab  = A  + b*SS*SS;
    for (int t = tid; t < SS*ROWS; t += 256) {
        int j = t >> 4, il = t & 15;
        int e = eob[j*SS + il];
        cnd[t] = (Ab[j*SS + e] == 1);
    }
    __syncthreads();

    // half2 max-pool: thread = (dp 0..31, grp 0..7); grp owns rows 2*grp, +1
    {
        int dp = tid & 31, grp = tid >> 5;
        int r0 = grp*2, r1 = r0 + 1;
        __half2 z = __float2half2_rn(0.f);
        __half2 m0 = z, m1 = z;
#pragma unroll 8
        for (int j = 0; j < SS; j++) {
            __half2 xv = xs2[j*32 + dp];
            m0 = __hmax2(m0, cnd[j*ROWS + r0] ? xv : z);
            m1 = __hmax2(m1, cnd[j*ROWS + r1] ? xv : z);
        }
        float2 f0 = __half22float2(m0), f1 = __half22float2(m1);
        nm[r0*DD + dp*2]     = f0.x;  nm[r0*DD + dp*2 + 1] = f0.y;
        nm[r1*DD + dp*2]     = f1.x;  nm[r1*DD + dp*2 + 1] = f1.y;
    }
    __syncthreads();

    // h = prelu(x@Ws + nm@Wn); thread = (d, g4 0..3), 4 rows each
    int d = tid & 63, g4 = tid >> 6;
    const __half* xh = (const __half*)xs2;
    {
        float acc[4] = {0.f, 0.f, 0.f, 0.f};
        for (int c = 0; c < DD; c++) {
            float ws = Ws[c*DD + d], wn = Wn[c*DD + d];
#pragma unroll
            for (int t = 0; t < 4; t++) {
                int r = g4*4 + t;
                float xv = __half2float(xh[(ih*ROWS + r)*DD + c]);
                acc[t] = fmaf(xv, ws, acc[t]);
                acc[t] = fmaf(nm[r*DD + c], wn, acc[t]);
            }
        }
        float a1 = p1[d];
#pragma unroll
        for (int t = 0; t < 4; t++) {
            float v = acc[t];
            hs[(g4*4 + t)*DD + d] = v >= 0.f ? v : a1*v;
        }
    }
    __syncthreads();

    // fused q/k/v projection on the 16 rows
    {
        float aq[4], ak[4], av[4];
        float bqd = bq[d];
#pragma unroll
        for (int t = 0; t < 4; t++) { aq[t] = bqd; ak[t] = 0.f; av[t] = 0.f; }
        for (int c = 0; c < DD; c++) {
            float wq = Wq[c*DD + d], wk = Wk[c*DD + d], wv = Wv[c*DD + d];
#pragma unroll
            for (int t = 0; t < 4; t++) {
                float hv = hs[(g4*4 + t)*DD + c];
                aq[t] = fmaf(hv, wq, aq[t]);
                ak[t] = fmaf(hv, wk, ak[t]);
                av[t] = fmaf(hv, wv, av[t]);
            }
        }
#pragma unroll
        for (int t = 0; t < 4; t++) {
            int gi = (b*SS + ih*ROWS + g4*4 + t)*DD + d;
            g_q[gi] = aq[t];
            g_k[gi] = ak[t];
            g_v[gi] = av[t];
        }
    }
}

// ===== kernel 2: fused attention (logits + softmax + a@v) ==================
// grid (2, BB), 512 threads (16 warps); warp w handles j_local = w*4 .. +3
__global__ void __launch_bounds__(512) k_attn(const int* __restrict__ A,
                                              const float* __restrict__ we,
                                              const float* __restrict__ prelu2) {
    int b = blockIdx.y, jh = blockIdx.x;
    int tid = threadIdx.x, w = tid >> 5, lane = tid & 31;
    __shared__ __half2 ks2[SS*33];           // 16.9KB: 0.5*k[b], pad 33
    __shared__ __half2 vs2[SS*32];           // 16KB:  v[b]
    __shared__ unsigned int msk[64][4];      // 1KB:   activity bitmasks per j
    __shared__ __half2 qw2[16][32];          // 2KB:   0.5*q per warp
    __shared__ unsigned char slist[16][SS];  // 2KB
    __shared__ __half awb[16][2*SS];         // 8KB:   aw interleaved (j0,j1)
    __shared__ __half2 wes2[32];             // we half2
    __shared__ float wesf[DD];               // we f32

    const float2* kb = (const float2*)(g_k + b*SS*DD);
    const float2* vb = (const float2*)(g_v + b*SS*DD);
    for (int t = tid; t < SS*32; t += 512) {
        int row = t >> 5, dp = t & 31;
        float2 kf = kb[t];
        ks2[row*33 + dp] = __floats2half2_rn(0.5f*kf.x, 0.5f*kf.y);
        float2 vf = vb[t];
        vs2[t] = __floats2half2_rn(vf.x, vf.y);
    }
    if (tid < 32) {
        float2 wf = *(const float2*)&we[tid*2];
        wes2[tid] = __floats2half2_rn(wf.x, wf.y);
    }
    if (tid >= 64 && tid < 128) wesf[tid - 64] = we[tid - 64];
    if (tid >= 128 && tid < 384) {
        int t = tid - 128;
        int jl = t >> 2, ii = t & 3;
        const int* Ac = A + (b*SS + ii*32)*SS + jh*64 + jl;
        unsigned m = 0;
#pragma unroll
        for (int l = 0; l < 32; l++) m |= (unsigned)(Ac[l*SS] == 1) << l;
        msk[jl][ii] = m;
    }
    __syncthreads();

    float e0;
    {
        float s = 0.f;
#pragma unroll
        for (int c = 0; c < DD; c++) s += wesf[c];
        e0 = 0.5f * s;                       // logit of an inactive edge
    }
    float2 pr = *(const float2*)&prelu2[lane*2];

    for (int pair = 0; pair < 2; pair++) {
        // ---- phase A: logits + softmax for j(par=0) and j(par=1) ----
        for (int par = 0; par < 2; par++) {
            int jl = (w << 2) + (pair << 1) + par;
            int j  = (jh << 6) + jl;
            {
                float2 qf = *(const float2*)&g_q[(b*SS + j)*DD + lane*2];
                qw2[w][lane] = __floats2half2_rn(0.5f*qf.x, 0.5f*qf.y);
            }
            __syncwarp();

            // compaction from bitmask
            int n = 0;
#pragma unroll
            for (int ii = 0; ii < 4; ii++) {
                unsigned m = msk[jl][ii];
                if ((m >> lane) & 1u)
                    slist[w][n + __popc(m & ((1u << lane) - 1u))] =
                        (unsigned char)(ii*32 + lane);
                n += __popc(m);
            }
            __syncwarp();
            int nIter = (n + 31) >> 5;

            float sreg[4];
#pragma unroll
            for (int it = 0; it < 4; it++) {
                sreg[it] = -1e30f;
                if (it < nIter) {
                    int idx = (it << 5) + lane;
                    bool val = idx < n;
                    int i = val ? (int)slist[w][idx] : lane;
                    const __half2* kr = &ks2[i*33];
                    float s0 = 0.f, s1 = 0.f;
#pragma unroll
                    for (int c8 = 0; c8 < 4; c8++) {
                        __half2 sacc = __float2half2_rn(0.f);
#pragma unroll
                        for (int dd = c8*8; dd < c8*8 + 8; dd++) {
                            __half2 z = __hadd2(kr[dd], qw2[w][dd]);
                            sacc = __hfma2(wes2[dd], tanh2_fast(z), sacc);
                        }
                        float2 f = __half22float2(sacc);
                        s0 += f.x; s1 += f.y;
                    }
                    if (val) sreg[it] = fmaf(0.5f, s0 + s1, e0);
                }
            }

            float mx = e0;
#pragma unroll
            for (int it = 0; it < 4; it++)
                if (it < nIter) mx = fmaxf(mx, warp_max(sreg[it]));
            float sum = (float)(SS - n) * __expf(e0 - mx);
            float preg[4];
#pragma unroll
            for (int it = 0; it < 4; it++)
                if (it < nIter) { preg[it] = __expf(sreg[it] - mx); sum += warp_sum(preg[it]); }
            float inv = __fdividef(1.f, sum);
            float a0 = __expf(e0 - mx) * inv;

            // dense fill with a0, then scatter active weights
            __half ha0 = __float2half(a0);
#pragma unroll
            for (int k2 = 0; k2 < 4; k2++)
                awb[w][2*(lane + 32*k2) + par] = ha0;
            __syncwarp();
#pragma unroll
            for (int it = 0; it < 4; it++)
                if (it < nIter) {
                    int idx = (it << 5) + lane;
                    if (idx < n)
                        awb[w][2*(int)slist[w][idx] + par] = __float2half(preg[it]*inv);
                }
            __syncwarp();
        }

        // ---- phase B: h2 for the two j's, v shared across both ----
        int j0 = (jh << 6) + (w << 2) + (pair << 1), j1 = j0 + 1;
        float x0 = 0.f, y0 = 0.f, x1 = 0.f, y1 = 0.f;
#pragma unroll 8
        for (int i = 0; i < SS; i++) {
            float2 vf = __half22float2(vs2[i*32 + lane]);
            __half2 aw2 = *(__half2*)&awb[w][2*i];
            float2 af = __half22float2(aw2);
            x0 = fmaf(af.x, vf.x, x0); y0 = fmaf(af.x, vf.y, y0);
            x1 = fmaf(af.y, vf.x, x1); y1 = fmaf(af.y, vf.y, y1);
        }
        float2 o0, o1;
        o0.x = x0 >= 0.f ? x0 : pr.x*x0;  o0.y = y0 >= 0.f ? y0 : pr.y*y0;
        o1.x = x1 >= 0.f ? x1 : pr.x*x1;  o1.y = y1 >= 0.f ? y1 : pr.y*y1;
        *(float2*)&g_h2[(b*SS + j0)*DD + lane*2] = o0;
        *(float2*)&g_h2[(b*SS + j1)*DD + lane*2] = o1;
        __syncwarp();
    }
}

// ===== kernel 3: full readout per b (eatt + softmax + sum + W_sr) ==========
// grid BB, 512 threads (16 warps); warp w owns s-rows w*8 .. +7 for eatt;
// lane owns d-pair {2*lane, 2*lane+1}. h2[b] and Wu staged in smem.
__global__ void __launch_bounds__(512) k_ro(
        const int* __restrict__ last_nodes,
        const float* __restrict__ Wu,  const float* __restrict__ bu,
        const float* __restrict__ Wvr, const float* __restrict__ wer,
        const float* __restrict__ prelu3, const float* __restrict__ W_sr,
        float* __restrict__ out) {
    int b = blockIdx.x;
    int tid = threadIdx.x, w = tid >> 5, lane = tid & 31;
    __shared__ float h2s[SS*DD];             // 32KB
    __shared__ float2 wu2[DD*32];            // 16KB: Wu[c][dpair]
    __shared__ float xlast[DD], xv[DD], eatt[SS], outv[DD];
    __shared__ float red[4];
    __shared__ float psum[8][DD];

    const float4* hb4 = (const float4*)(g_h2 + b*SS*DD);
    for (int t = tid; t < SS*DD/4; t += 512) ((float4*)h2s)[t] = hb4[t];
    const float2* Wuf2 = (const float2*)Wu;
    for (int t = tid; t < DD*32; t += 512) wu2[t] = Wuf2[t];
    int ln = last_nodes[b];
    __syncthreads();
    if (tid < DD) xlast[tid] = h2s[ln*DD + tid];
    __syncthreads();
    if (tid < DD) {
        float a = 0.f;
#pragma unroll
        for (int c = 0; c < DD; c++) a = fmaf(xlast[c], Wvr[c*DD + tid], a);
        xv[tid] = a;
    }
    __syncthreads();

    // ---- eatt: warp w owns rows w*8 .. +7, lane owns d-pair ----
    {
        float bx = bu[2*lane]     + xv[2*lane];
        float by = bu[2*lane + 1] + xv[2*lane + 1];
        float2 acc[8];
#pragma unroll
        for (int r = 0; r < 8; r++) { acc[r].x = bx; acc[r].y = by; }
        const float* hrow = &h2s[(w*8)*DD];
#pragma unroll 16
        for (int c = 0; c < DD; c++) {
            float2 wuc = wu2[c*32 + lane];
#pragma unroll
            for (int r = 0; r < 8; r++) {
                float h = hrow[r*DD + c];
                acc[r].x = fmaf(h, wuc.x, acc[r].x);
                acc[r].y = fmaf(h, wuc.y, acc[r].y);
            }
        }
        float wx = wer[2*lane], wy = wer[2*lane + 1];
#pragma unroll
        for (int r = 0; r < 8; r++) {
            float val = fmaf(wx, fast_sigmoid(acc[r].x), wy * fast_sigmoid(acc[r].y));
            val = warp_sum(val);
            if (lane == 0) eatt[w*8 + r] = val;
        }
    }
    __syncthreads();

    // ---- softmax over 128 values (threads 0..127 carry; all hit barriers) --
    {
        float ev = (tid < SS) ? eatt[tid] : -1e30f;
        float m = warp_max(ev);
        if (lane == 0 && tid < SS) red[tid >> 5] = m;
        __syncthreads();
        float mx = fmaxf(fmaxf(red[0], red[1]), fmaxf(red[2], red[3]));
        float ex = (tid < SS) ? __expf(ev - mx) : 0.f;
        __syncthreads();
        float sv = warp_sum(ex);
        if (lane == 0 && tid < SS) red[tid >> 5] = sv;
        __syncthreads();
        float tot = red[0] + red[1] + red[2] + red[3];
        if (tid < SS) eatt[tid] = ex * __fdividef(1.f, tot);
    }
    __syncthreads();

    // ---- out[d] = prelu3( sum_s alpha[s]*h2s[s][d] ) ----
    {
        int d = tid & 63, grp = tid >> 6;    // 8 groups of 16 s
        float acc = 0.f;
#pragma unroll
        for (int t = 0; t < 16; t++) {
            int s = grp*16 + t;
            acc = fmaf(eatt[s], h2s[s*DD + d], acc);
        }
        psum[grp][d] = acc;
    }
    __syncthreads();
    if (tid < DD) {
        float sm = 0.f;
#pragma unroll
        for (int g = 0; g < 8; g++) sm += psum[g][tid];
        float a = prelu3[tid];
        outv[tid] = sm >= 0.f ? sm : a * sm;
    }
    __syncthreads();
    if (tid < DD) {
        float a = 0.f;
#pragma unroll
        for (int c = 0; c < DD; c++) {
            a = fmaf(outv[c],  W_sr[c*DD + tid], a);
            a = fmaf(xlast[c], W_sr[(DD + c)*DD + tid], a);
        }
        out[b*DD + tid] = a;
    }
}

extern "C" void kernel_launch(void* const* d_in, const int* in_sizes, int n_in,
                              void* d_out, int out_size) {
    const int*   items      = (const int*)  d_in[0];
    const int*   A          = (const int*)  d_in[1];
    const int*   eo         = (const int*)  d_in[2];
    const int*   last_nodes = (const int*)  d_in[3];
    // d_in[4] = mask (all true)
    const float* emb        = (const float*)d_in[5];
    const float* W_self     = (const float*)d_in[6];
    const float* W_neigh    = (const float*)d_in[7];
    const float* prelu1     = (const float*)d_in[8];
    const float* Wq         = (const float*)d_in[9];
    const float* bq         = (const float*)d_in[10];
    const float* Wk         = (const float*)d_in[11];
    const float* Wv         = (const float*)d_in[12];
    const float* we         = (const float*)d_in[13];
    const float* prelu2     = (const float*)d_in[14];
    const float* Wu         = (const float*)d_in[15];
    const float* bu         = (const float*)d_in[16];
    const float* Wvr        = (const float*)d_in[17];
    const float* wer        = (const float*)d_in[18];
    const float* prelu3     = (const float*)d_in[19];
    const float* W_sr       = (const float*)d_in[20];
    float* out = (float*)d_out;

    k_eopa<<<dim3(8, BB), 256>>>(items, A, eo, emb, W_self, W_neigh, prelu1,
                                 Wq, bq, Wk, Wv);
    k_attn<<<dim3(2, BB), 512>>>(A, we, prelu2);
    k_ro<<<BB, 512>>>(last_nodes, Wu, bu, Wvr, wer, prelu3, W_sr, out);
}